// round 13
// baseline (speedup 1.0000x reference)
#include <cuda_runtime.h>
#include <cuda_fp16.h>
#include <cstdint>

#define NN 25000
#define NE 400000
#define HD 128
#define LN_EPS 1e-5f

// ================= device scratch =================
__device__ int   g_src[NE];
__device__ int   g_dst[NE];
__device__ int   g_is64;
__device__ float g_eA[(size_t)NE * HD];
__device__ float g_eB[(size_t)NE * HD];
__device__ float g_agg[(size_t)NN * HD];
__device__ float g_x[(size_t)NN * HD];

// fp16 hi/lo weight pools, [n=128][Kpad] row-major per matrix
#define POOL_ELEMS 335872
__device__ __align__(16) __half g_wh[POOL_ELEMS];
__device__ __align__(16) __half g_wl[POOL_ELEMS];

// ================= smem layout (dynamic, bytes) =================
// M=256 rows per CTA. 64-col tiles, row stride 144 B.
#define LDT      144u
#define WB(i)    ((uint32_t)(i) * 36864u)              // [0, 73728)
#define SL(i)    (73728u + (uint32_t)(i) * 73728u)     // [73728, 221184)
#define A_PAIR   36864u
#define W_PAIR   18432u
#define SMEM_DYN 221184
#define ROWS_CTA 256
// f32 LN staging: floats at byte 73728, stride 130 (256*130*4 = 133120 B fits)

// ================= helpers =================
__device__ __forceinline__ uint32_t smem_u32(const void* p) {
    uint32_t a;
    asm("{ .reg .u64 t; cvta.to.shared.u64 t, %1; cvt.u32.u64 %0, t; }"
        : "=r"(a) : "l"(p));
    return a;
}
__device__ __forceinline__ void ldsm4(uint32_t addr, uint32_t* r) {
    asm volatile("ldmatrix.sync.aligned.m8n8.x4.shared.b16 {%0,%1,%2,%3}, [%4];"
                 : "=r"(r[0]), "=r"(r[1]), "=r"(r[2]), "=r"(r[3]) : "r"(addr));
}
__device__ __forceinline__ void mma16816(float* d, const uint32_t* a,
                                         uint32_t b0, uint32_t b1) {
    asm("mma.sync.aligned.m16n8k16.row.col.f32.f16.f16.f32 "
        "{%0,%1,%2,%3}, {%4,%5,%6,%7}, {%8,%9}, {%0,%1,%2,%3};"
        : "+f"(d[0]), "+f"(d[1]), "+f"(d[2]), "+f"(d[3])
        : "r"(a[0]), "r"(a[1]), "r"(a[2]), "r"(a[3]), "r"(b0), "r"(b1));
}
__device__ __forceinline__ void cp16(uint32_t dst, const void* src) {
    asm volatile("cp.async.cg.shared.global [%0], [%1], 16;"
                 :: "r"(dst), "l"(src));
}
#define CP_COMMIT() asm volatile("cp.async.commit_group;")
#define CP_WAIT0()  asm volatile("cp.async.wait_group 0;" ::: "memory")
// 6-instruction hi/lo split using packed cvts
__device__ __forceinline__ void pack_pair(float a, float b, uint32_t& hi, uint32_t& lo) {
    __half2 H = __floats2half2_rn(a, b);
    float2 hf = __half22float2(H);
    __half2 L = __floats2half2_rn(a - hf.x, b - hf.y);
    hi = *reinterpret_cast<uint32_t*>(&H);
    lo = *reinterpret_cast<uint32_t*>(&L);
}
__device__ __forceinline__ float silu(float v) {
    return __fdividef(v, 1.f + __expf(-v));
}

// ================= index prep =================
__global__ void detect_kernel(const int* __restrict__ raw) {
    __shared__ int cnt;
    if (threadIdx.x == 0) cnt = 0;
    __syncthreads();
    int c = 0;
    for (int t = threadIdx.x; t < 1024; t += blockDim.x)
        if (raw[2 * t + 1] != 0) c++;
    atomicAdd(&cnt, c);
    __syncthreads();
    if (threadIdx.x == 0) g_is64 = (cnt < 16) ? 1 : 0;
}
__global__ void convert_kernel(const int* __restrict__ raw) {
    int i = blockIdx.x * blockDim.x + threadIdx.x;
    if (i >= NE) return;
    int s, d;
    if (g_is64) {
        const long long* p = (const long long*)raw;
        s = (int)p[i];
        d = (int)p[NE + i];
    } else {
        s = raw[i];
        d = raw[NE + i];
    }
    if ((unsigned)s >= NN) s = 0;
    if ((unsigned)d >= NN) d = 0;
    g_src[i] = s;
    g_dst[i] = d;
}

// ================= weight split prep =================
#define NJOBS 15
struct WJob { const float* src; int Ksrc; int Kpad; int dst; };
struct WJobs { WJob j[NJOBS]; };
__global__ void conv_w_kernel(WJobs jobs) {
    WJob jb = jobs.j[blockIdx.y];
    int idx = blockIdx.x * 256 + threadIdx.x;
    if (idx >= 128 * jb.Kpad) return;
    int n = idx / jb.Kpad, k = idx % jb.Kpad;
    float v = (k < jb.Ksrc) ? jb.src[(size_t)k * 128 + n] : 0.f;
    __half h = __float2half_rn(v);
    float r = v - __half2float(h);
    g_wh[(size_t)jb.dst + (size_t)n * jb.Kpad + k] = h;
    g_wl[(size_t)jb.dst + (size_t)n * jb.Kpad + k] = __float2half_rn(r);
}

// ================= A gather (one 128-row half of the 256-row tile) =================
template <int MODE>
__device__ __forceinline__ void a_load(const float* __restrict__ in0,
                                       const float* __restrict__ in1,
                                       int chunk, int half, int row0, int rows,
                                       int t, float4* v) {
    const int r = (t >> 2) + half * 128;
    const int kh = (t & 3) << 4;          // 0,16,32,48
    const int gk = chunk * 64 + kh;
    const int row = row0 + r;
    const float* src = nullptr;
    if (MODE == 0) {
        if (kh == 0 && row < rows) src = in0 + (size_t)row * 16;
    } else if (MODE == 1) {
        if (row < rows) {
            int sect = gk >> 7;
            int coff = gk & 127;
            if (sect == 0)      src = in0 + (size_t)g_dst[row] * HD + coff;
            else if (sect == 1) src = in0 + (size_t)g_src[row] * HD + coff;
            else                src = in1 + (size_t)row * HD + coff;
        }
    } else {
        if (row < rows) {
            int sect = gk >> 7;
            int coff = gk & 127;
            src = (sect ? in1 : in0) + (size_t)row * HD + coff;
        }
    }
    v[0] = v[1] = v[2] = v[3] = make_float4(0.f, 0.f, 0.f, 0.f);
    if (src) {
        v[0] = *(const float4*)(src);
        v[1] = *(const float4*)(src + 4);
        v[2] = *(const float4*)(src + 8);
        v[3] = *(const float4*)(src + 12);
    }
}

__device__ __forceinline__ void a_store(char* sm, uint32_t slotHi, int half,
                                        int t, const float4* v) {
    const int r = (t >> 2) + half * 128;
    const int kh = (t & 3) << 4;
    const uint32_t rbase = (uint32_t)r * LDT;
#pragma unroll
    for (int g = 0; g < 2; g++) {
        uint32_t h[4], l[4];
        pack_pair(v[2 * g].x,     v[2 * g].y,     h[0], l[0]);
        pack_pair(v[2 * g].z,     v[2 * g].w,     h[1], l[1]);
        pack_pair(v[2 * g + 1].x, v[2 * g + 1].y, h[2], l[2]);
        pack_pair(v[2 * g + 1].z, v[2 * g + 1].w, h[3], l[3]);
        uint32_t off = rbase + (uint32_t)(kh + g * 8) * 2u;
        *(uint4*)(sm + slotHi + off)          = make_uint4(h[0], h[1], h[2], h[3]);
        *(uint4*)(sm + slotHi + A_PAIR + off) = make_uint4(l[0], l[1], l[2], l[3]);
    }
}

// W tile (128 n x 64 k) via cp.async; Kpad may be < 64 (emb L1)
__device__ __forceinline__ void load_w_async(uint32_t sb, uint32_t wb,
                                             int wofs, int kc, int Kpad, int t) {
    const int n = t >> 2;
    const int kh = (t & 3) << 4;
    if (n >= 128) return;
    if (kh >= Kpad) return;
    const __half* ph = g_wh + wofs + (size_t)n * Kpad + kc + kh;
    const __half* pl = g_wl + wofs + (size_t)n * Kpad + kc + kh;
    const uint32_t nb = (uint32_t)n * LDT;
#pragma unroll
    for (int g = 0; g < 2; g++) {
        uint32_t off = nb + (uint32_t)(kh + g * 8) * 2u;
        cp16(sb + wb + off, ph + g * 8);
        cp16(sb + wb + W_PAIR + off, pl + g * 8);
    }
}

// ================= warp MMA: 32(M) x 64(N), nb-pair grouping (dep distance 8) =====
template <int K16S>
__device__ __forceinline__ void mma_chunk(uint32_t sb, uint32_t aHi, uint32_t wB,
                                          float (&acc)[2][8][4], int m0, int n0, int lane) {
    const uint32_t aLo = aHi + A_PAIR;
    const uint32_t wLo = wB + W_PAIR;
    const int rowA = m0 + (lane & 15);
    const int kselA = (lane >> 4) << 3;
    const uint32_t aB0 = (uint32_t)rowA * LDT;
    const uint32_t aB1 = aB0 + 16u * LDT;
    const int rowB = n0 + (lane & 7) + (((lane >> 4) & 1) << 3);
    const int kselB = ((lane >> 3) & 1) << 3;
#pragma unroll
    for (int ks = 0; ks < K16S; ks++) {
        const int k16 = ks * 16;
        uint32_t ah[2][4], al[2][4];
        uint32_t ak = (uint32_t)(k16 + kselA) * 2u;
        ldsm4(sb + aHi + aB0 + ak, ah[0]);
        ldsm4(sb + aHi + aB1 + ak, ah[1]);
        ldsm4(sb + aLo + aB0 + ak, al[0]);
        ldsm4(sb + aLo + aB1 + ak, al[1]);
        uint32_t bk = (uint32_t)(k16 + kselB) * 2u;
#pragma unroll
        for (int np = 0; np < 2; np++) {       // nb pairs {0,1}, {2,3}
            uint32_t bh[2][4], bl[2][4];
#pragma unroll
            for (int p = 0; p < 2; p++) {
                uint32_t bb = (uint32_t)(rowB + (np * 2 + p) * 16) * LDT;
                ldsm4(sb + wB + bb + bk, bh[p]);
                ldsm4(sb + wLo + bb + bk, bl[p]);
            }
            // pass 1: Ah x Wh — 8 independent MMAs
#pragma unroll
            for (int p = 0; p < 2; p++)
#pragma unroll
                for (int mi = 0; mi < 2; mi++) {
                    int jb = (np * 2 + p) * 2;
                    mma16816(acc[mi][jb],     ah[mi], bh[p][0], bh[p][1]);
                    mma16816(acc[mi][jb + 1], ah[mi], bh[p][2], bh[p][3]);
                }
            // pass 2: Al x Wh
#pragma unroll
            for (int p = 0; p < 2; p++)
#pragma unroll
                for (int mi = 0; mi < 2; mi++) {
                    int jb = (np * 2 + p) * 2;
                    mma16816(acc[mi][jb],     al[mi], bh[p][0], bh[p][1]);
                    mma16816(acc[mi][jb + 1], al[mi], bh[p][2], bh[p][3]);
                }
            // pass 3: Ah x Wl
#pragma unroll
            for (int p = 0; p < 2; p++)
#pragma unroll
                for (int mi = 0; mi < 2; mi++) {
                    int jb = (np * 2 + p) * 2;
                    mma16816(acc[mi][jb],     ah[mi], bl[p][0], bl[p][1]);
                    mma16816(acc[mi][jb + 1], ah[mi], bl[p][2], bl[p][3]);
                }
        }
    }
}

__device__ __forceinline__ void zero_acc(float (&acc)[2][8][4]) {
#pragma unroll
    for (int mi = 0; mi < 2; mi++)
#pragma unroll
        for (int j = 0; j < 8; j++)
#pragma unroll
            for (int e = 0; e < 4; e++) acc[mi][j][e] = 0.f;
}

// ================= epilogues =================
__device__ __forceinline__ void epi_silu(char* sm, float (&acc)[2][8][4],
                                         const float* __restrict__ bias,
                                         int m0, int n0, int lane) {
    const int cq = (lane & 3) << 1;
    const int r0l = lane >> 2;
#pragma unroll
    for (int mi = 0; mi < 2; mi++)
#pragma unroll
        for (int j = 0; j < 8; j++) {
            int c = n0 + j * 8 + cq;
            float b0 = bias[c], b1 = bias[c + 1];
            uint32_t hiT = SL(c >> 6);
            int hc = c & 63;
#pragma unroll
            for (int h = 0; h < 2; h++) {
                float v0 = silu(acc[mi][j][2 * h] + b0);
                float v1 = silu(acc[mi][j][2 * h + 1] + b1);
                uint32_t hi, lo;
                pack_pair(v0, v1, hi, lo);
                int r = m0 + mi * 16 + r0l + 8 * h;
                uint32_t off = (uint32_t)r * LDT + (uint32_t)(hc * 2);
                *(uint32_t*)(sm + hiT + off)          = hi;
                *(uint32_t*)(sm + hiT + A_PAIR + off) = lo;
            }
        }
}

__device__ __forceinline__ void epi_ln(char* sm, float (&acc)[2][8][4],
                                       const float* __restrict__ bias,
                                       const float* __restrict__ gam,
                                       const float* __restrict__ bet,
                                       float (*sRed)[ROWS_CTA][2],
                                       int m0, int n0, int wn, int lane) {
    const int cq = (lane & 3) << 1;
    const int r0l = lane >> 2;
    float s[2][2] = {{0.f, 0.f}, {0.f, 0.f}};
    float q[2][2] = {{0.f, 0.f}, {0.f, 0.f}};
#pragma unroll
    for (int mi = 0; mi < 2; mi++)
#pragma unroll
        for (int j = 0; j < 8; j++) {
            int c = n0 + j * 8 + cq;
            float b0 = bias[c], b1 = bias[c + 1];
#pragma unroll
            for (int h = 0; h < 2; h++) {
                float v0 = acc[mi][j][2 * h] + b0;
                float v1 = acc[mi][j][2 * h + 1] + b1;
                s[mi][h] += v0 + v1;
                q[mi][h] += v0 * v0 + v1 * v1;
            }
        }
#pragma unroll
    for (int o = 1; o <= 2; o <<= 1)
#pragma unroll
        for (int mi = 0; mi < 2; mi++)
#pragma unroll
            for (int h = 0; h < 2; h++) {
                s[mi][h] += __shfl_xor_sync(0xffffffffu, s[mi][h], o);
                q[mi][h] += __shfl_xor_sync(0xffffffffu, q[mi][h], o);
            }
    if ((lane & 3) == 0) {
#pragma unroll
        for (int mi = 0; mi < 2; mi++)
#pragma unroll
            for (int h = 0; h < 2; h++) {
                int r = m0 + mi * 16 + r0l + 8 * h;
                sRed[wn][r][0] = s[mi][h];
                sRed[wn][r][1] = q[mi][h];
            }
    }
    __syncthreads();
    float mu[2][2], rs[2][2];
#pragma unroll
    for (int mi = 0; mi < 2; mi++)
#pragma unroll
        for (int h = 0; h < 2; h++) {
            int r = m0 + mi * 16 + r0l + 8 * h;
            float S = sRed[0][r][0] + sRed[1][r][0];
            float Q = sRed[0][r][1] + sRed[1][r][1];
            float m = S * (1.f / HD);
            float var = Q * (1.f / HD) - m * m;
            mu[mi][h] = m;
            rs[mi][h] = rsqrtf(var + LN_EPS);
        }
    float* so = (float*)(sm + 73728u);
#pragma unroll
    for (int mi = 0; mi < 2; mi++)
#pragma unroll
        for (int j = 0; j < 8; j++) {
            int c = n0 + j * 8 + cq;
            float b0 = bias[c], b1 = bias[c + 1];
            float g0 = gam[c], g1 = gam[c + 1];
            float e0 = bet[c], e1 = bet[c + 1];
#pragma unroll
            for (int h = 0; h < 2; h++) {
                int r = m0 + mi * 16 + r0l + 8 * h;
                float v0 = acc[mi][j][2 * h] + b0;
                float v1 = acc[mi][j][2 * h + 1] + b1;
                so[r * 130 + c]     = (v0 - mu[mi][h]) * rs[mi][h] * g0 + e0;
                so[r * 130 + c + 1] = (v1 - mu[mi][h]) * rs[mi][h] * g1 + e1;
            }
        }
}

// ================= fused MLP kernel (512 threads, M=256, pipelined) =================
template <int MODE, int NCH, int K16S1>
__global__ __launch_bounds__(512, 1) void mma_mlp(
    const float* __restrict__ in0, const float* __restrict__ in1,
    int o1, int o2, int o3, int Kpad1,
    const float* __restrict__ b1, const float* __restrict__ b2,
    const float* __restrict__ b3, const float* __restrict__ gam,
    const float* __restrict__ bet,
    const float* __restrict__ resid, float* __restrict__ out, int rows) {
    extern __shared__ char sm[];
    __shared__ float sRed[2][ROWS_CTA][2];
    const int t = threadIdx.x;
    const uint32_t sb = smem_u32(sm);
    const int lane = t & 31, w = t >> 5;
    const int m0 = (w & 7) * 32, n0 = (w >> 3) * 64, wn = w >> 3;
    const int row0 = blockIdx.x * ROWS_CTA;
    float acc[2][8][4];
    float4 v[4];

    // ---- layer 1: pipelined 64-col chunks; gather + W latency hidden by MMA ----
    zero_acc(acc);
    for (int c = 0; c < NCH; c++) {
        __syncthreads();                       // SL(c&1), WB(c&1) free
        a_load<MODE>(in0, in1, c, 0, row0, rows, t, v);   // LDGs in flight
        load_w_async(sb, WB(c & 1), o1, c * 64, Kpad1, t);
        CP_COMMIT();
        if (c > 0) mma_chunk<K16S1>(sb, SL((c - 1) & 1), WB((c - 1) & 1), acc, m0, n0, lane);
        a_store((char*)sm, SL(c & 1), 0, t, v);           // consumes completed LDGs
        a_load<MODE>(in0, in1, c, 1, row0, rows, t, v);
        a_store((char*)sm, SL(c & 1), 1, t, v);
        CP_WAIT0();
    }
    __syncthreads();
    mma_chunk<K16S1>(sb, SL((NCH - 1) & 1), WB((NCH - 1) & 1), acc, m0, n0, lane);
    __syncthreads();

    // ---- layer 2 ----
    load_w_async(sb, WB(0), o2, 0, 128, t);
    load_w_async(sb, WB(1), o2, 64, 128, t);
    CP_COMMIT();
    epi_silu((char*)sm, acc, b1, m0, n0, lane);
    zero_acc(acc);
    CP_WAIT0();
    __syncthreads();
    mma_chunk<4>(sb, SL(0), WB(0), acc, m0, n0, lane);
    mma_chunk<4>(sb, SL(1), WB(1), acc, m0, n0, lane);
    __syncthreads();

    // ---- layer 3 ----
    load_w_async(sb, WB(0), o3, 0, 128, t);
    load_w_async(sb, WB(1), o3, 64, 128, t);
    CP_COMMIT();
    epi_silu((char*)sm, acc, b2, m0, n0, lane);
    zero_acc(acc);
    CP_WAIT0();
    __syncthreads();
    mma_chunk<4>(sb, SL(0), WB(0), acc, m0, n0, lane);
    mma_chunk<4>(sb, SL(1), WB(1), acc, m0, n0, lane);
    __syncthreads();
    epi_ln((char*)sm, acc, b3, gam, bet, sRed, m0, n0, wn, lane);
    __syncthreads();

    // ---- residual + coalesced store ----
    const float* so = (const float*)(sm + 73728u);
    const int col = t & 127;
    for (int r = (t >> 7); r < ROWS_CTA; r += 4) {
        int row = row0 + r;
        if (row < rows) {
            float y = so[r * 130 + col];
            if (MODE != 0) y += resid[(size_t)row * HD + col];
            out[(size_t)row * HD + col] = y;
        }
    }
}

// ================= aggregation =================
__global__ void zero_agg_kernel() {
    size_t i = (size_t)blockIdx.x * blockDim.x + threadIdx.x;
    if (i < (size_t)NN * HD) g_agg[i] = 0.f;
}
__global__ void scatter_kernel(const float* __restrict__ e) {
    size_t i = (size_t)blockIdx.x * blockDim.x + threadIdx.x;
    if (i >= (size_t)NE * (HD / 4)) return;
    int edge = (int)(i >> 5);
    int c = (int)(i & 31) << 2;
    float4 val = *(const float4*)(e + (size_t)edge * HD + c);
    float* p = g_agg + (size_t)g_dst[edge] * HD + c;
    asm volatile("red.global.add.v4.f32 [%0], {%1, %2, %3, %4};"
                 :: "l"(p), "f"(val.x), "f"(val.y), "f"(val.z), "f"(val.w)
                 : "memory");
}

// ================= launch =================
extern "C" void kernel_launch(void* const* d_in, const int* in_sizes, int n_in,
                              void* d_out, int out_size) {
    const float* x_in    = (const float*)d_in[0];
    const int*   eidx    = (const int*)d_in[1];
    const float* eattr   = (const float*)d_in[2];
    const float* emb_W1  = (const float*)d_in[3];
    const float* emb_b1  = (const float*)d_in[4];
    const float* emb_W2  = (const float*)d_in[5];
    const float* emb_b2  = (const float*)d_in[6];
    const float* emb_W3  = (const float*)d_in[7];
    const float* emb_b3  = (const float*)d_in[8];
    const float* emb_g   = (const float*)d_in[9];
    const float* emb_be  = (const float*)d_in[10];
    const float* edge_W1 = (const float*)d_in[11];
    const float* edge_b1 = (const float*)d_in[12];
    const float* edge_W2 = (const float*)d_in[13];
    const float* edge_b2 = (const float*)d_in[14];
    const float* edge_W3 = (const float*)d_in[15];
    const float* edge_b3 = (const float*)d_in[16];
    const float* edge_g  = (const float*)d_in[17];
    const float* edge_be = (const float*)d_in[18];
    const float* node_W1 = (const float*)d_in[19];
    const float* node_b1 = (const float*)d_in[20];
    const float* node_W2 = (const float*)d_in[21];
    const float* node_b2 = (const float*)d_in[22];
    const float* node_W3 = (const float*)d_in[23];
    const float* node_b3 = (const float*)d_in[24];
    const float* node_g  = (const float*)d_in[25];
    const float* node_be = (const float*)d_in[26];

    float* out_x = (float*)d_out;
    float* out_e = (float*)d_out + (size_t)NN * HD;

    float *eA, *eB, *agg, *xbuf;
    cudaGetSymbolAddress((void**)&eA, g_eA);
    cudaGetSymbolAddress((void**)&eB, g_eB);
    cudaGetSymbolAddress((void**)&agg, g_agg);
    cudaGetSymbolAddress((void**)&xbuf, g_x);

    cudaFuncSetAttribute((const void*)mma_mlp<0, 1, 1>, cudaFuncAttributeMaxDynamicSharedMemorySize, SMEM_DYN);
    cudaFuncSetAttribute((const void*)mma_mlp<1, 6, 4>, cudaFuncAttributeMaxDynamicSharedMemorySize, SMEM_DYN);
    cudaFuncSetAttribute((const void*)mma_mlp<2, 4, 4>, cudaFuncAttributeMaxDynamicSharedMemorySize, SMEM_DYN);

    // index prep (clamped)
    detect_kernel<<<1, 256>>>(eidx);
    convert_kernel<<<(NE + 255) / 256, 256>>>(eidx);

    // pool offsets (elements)
    const int oEmb1 = 0, oEmb2 = 8192, oEmb3 = 24576;
    int oE1[2], oE2[2], oE3[2], oN1[2], oN2[2], oN3[2];
    int base = 40960;
    for (int l = 0; l < 2; l++) {
        oE1[l] = base;
        oE2[l] = base + 49152;
        oE3[l] = base + 65536;
        oN1[l] = base + 81920;
        oN2[l] = base + 114688;
        oN3[l] = base + 131072;
        base += 147456;
    }

    WJobs jobs;
    int ji = 0;
    jobs.j[ji++] = {emb_W1, 16, 16, oEmb1};
    jobs.j[ji++] = {emb_W2, 128, 128, oEmb2};
    jobs.j[ji++] = {emb_W3, 128, 128, oEmb3};
    for (int l = 0; l < 2; l++) {
        jobs.j[ji++] = {edge_W1 + (size_t)l * 3 * HD * HD, 384, 384, oE1[l]};
        jobs.j[ji++] = {edge_W2 + (size_t)l * HD * HD, 128, 128, oE2[l]};
        jobs.j[ji++] = {edge_W3 + (size_t)l * HD * HD, 128, 128, oE3[l]};
        jobs.j[ji++] = {node_W1 + (size_t)l * 2 * HD * HD, 256, 256, oN1[l]};
        jobs.j[ji++] = {node_W2 + (size_t)l * HD * HD, 128, 128, oN2[l]};
        jobs.j[ji++] = {node_W3 + (size_t)l * HD * HD, 128, 128, oN3[l]};
    }
    dim3 cg((128 * 384 + 255) / 256, NJOBS);
    conv_w_kernel<<<cg, 256>>>(jobs);

    const int edge_blocks = (NE + ROWS_CTA - 1) / ROWS_CTA;   // 1563
    const int node_blocks = (NN + ROWS_CTA - 1) / ROWS_CTA;   // 98
    const int scat_blocks = (int)(((size_t)NE * (HD / 4) + 255) / 256);
    const int nthr_blocks = (int)(((size_t)NN * HD + 255) / 256);

    // edge embedding: e = MLP(edge_attr)
    mma_mlp<0, 1, 1><<<edge_blocks, 512, SMEM_DYN>>>(
        eattr, nullptr, oEmb1, oEmb2, oEmb3, 16,
        emb_b1, emb_b2, emb_b3, emb_g, emb_be, nullptr, eA, NE);

    const float* x_cur = x_in;
    float* e_cur = eA;
    for (int l = 0; l < 2; l++) {
        float* e_out = (l == 0) ? eB : out_e;
        float* x_out = (l == 0) ? xbuf : out_x;

        // e_new = MLP([x[dst] | x[src] | e]) + e
        mma_mlp<1, 6, 4><<<edge_blocks, 512, SMEM_DYN>>>(
            x_cur, e_cur, oE1[l], oE2[l], oE3[l], 384,
            edge_b1 + l * HD, edge_b2 + l * HD, edge_b3 + l * HD,
            edge_g + l * HD, edge_be + l * HD, e_cur, e_out, NE);

        // agg = segment_sum(e_new, dst)
        zero_agg_kernel<<<nthr_blocks, 256>>>();
        scatter_kernel<<<scat_blocks, 256>>>(e_out);

        // x = MLP([x | agg]) + x
        mma_mlp<2, 4, 4><<<node_blocks, 512, SMEM_DYN>>>(
            x_cur, agg, oN1[l], oN2[l], oN3[l], 256,
            node_b1 + l * HD, node_b2 + l * HD, node_b3 + l * HD,
            node_g + l * HD, node_be + l * HD, x_cur, x_out, NN);

        e_cur = e_out;
        x_cur = x_out;
    }
}

// round 14
// speedup vs baseline: 1.0405x; 1.0405x over previous
#include <cuda_runtime.h>
#include <cuda_fp16.h>
#include <cstdint>

#define NN 25000
#define NE 400000
#define HD 128
#define LN_EPS 1e-5f

// ================= device scratch =================
__device__ int   g_src[NE];
__device__ int   g_dst[NE];
__device__ int   g_is64;
__device__ float g_eA[(size_t)NE * HD];
__device__ float g_eB[(size_t)NE * HD];
__device__ float g_agg[(size_t)NN * HD];
__device__ float g_x[(size_t)NN * HD];

// fp16 hi/lo weight pools, [n=128][Kpad] row-major per matrix
#define POOL_ELEMS 335872
__device__ __align__(16) __half g_wh[POOL_ELEMS];
__device__ __align__(16) __half g_wl[POOL_ELEMS];

// ================= smem layout (dynamic, bytes) =================
// M=256 rows per CTA. 64-col tiles, row stride 144 B.
#define LDT      144u
#define WB(i)    ((uint32_t)(i) * 36864u)              // [0, 73728)
#define SL(i)    (73728u + (uint32_t)(i) * 73728u)     // [73728, 221184)
#define A_PAIR   36864u
#define W_PAIR   18432u
#define SMEM_DYN 221184
#define ROWS_CTA 256
// f32 LN staging: floats at byte 73728, stride 130 (256*130*4 = 133120 B fits)

// ================= helpers =================
__device__ __forceinline__ uint32_t smem_u32(const void* p) {
    uint32_t a;
    asm("{ .reg .u64 t; cvta.to.shared.u64 t, %1; cvt.u32.u64 %0, t; }"
        : "=r"(a) : "l"(p));
    return a;
}
__device__ __forceinline__ void ldsm4(uint32_t addr, uint32_t* r) {
    asm volatile("ldmatrix.sync.aligned.m8n8.x4.shared.b16 {%0,%1,%2,%3}, [%4];"
                 : "=r"(r[0]), "=r"(r[1]), "=r"(r[2]), "=r"(r[3]) : "r"(addr));
}
__device__ __forceinline__ void mma16816(float* d, const uint32_t* a,
                                         uint32_t b0, uint32_t b1) {
    asm("mma.sync.aligned.m16n8k16.row.col.f32.f16.f16.f32 "
        "{%0,%1,%2,%3}, {%4,%5,%6,%7}, {%8,%9}, {%0,%1,%2,%3};"
        : "+f"(d[0]), "+f"(d[1]), "+f"(d[2]), "+f"(d[3])
        : "r"(a[0]), "r"(a[1]), "r"(a[2]), "r"(a[3]), "r"(b0), "r"(b1));
}
__device__ __forceinline__ void cp16(uint32_t dst, const void* src) {
    asm volatile("cp.async.cg.shared.global [%0], [%1], 16;"
                 :: "r"(dst), "l"(src));
}
#define CP_COMMIT() asm volatile("cp.async.commit_group;")
#define CP_WAIT0()  asm volatile("cp.async.wait_group 0;" ::: "memory")
__device__ __forceinline__ void pack_pair(float a, float b, uint32_t& hi, uint32_t& lo) {
    __half ha = __float2half_rn(a), hb = __float2half_rn(b);
    float ra = a - __half2float(ha);
    float rb = b - __half2float(hb);
    __half2 H = __halves2half2(ha, hb);
    __half2 L = __floats2half2_rn(ra, rb);
    hi = *reinterpret_cast<uint32_t*>(&H);
    lo = *reinterpret_cast<uint32_t*>(&L);
}
__device__ __forceinline__ float silu(float v) {
    return __fdividef(v, 1.f + __expf(-v));
}

// ================= index prep =================
__global__ void detect_kernel(const int* __restrict__ raw) {
    __shared__ int cnt;
    if (threadIdx.x == 0) cnt = 0;
    __syncthreads();
    int c = 0;
    for (int t = threadIdx.x; t < 1024; t += blockDim.x)
        if (raw[2 * t + 1] != 0) c++;
    atomicAdd(&cnt, c);
    __syncthreads();
    if (threadIdx.x == 0) g_is64 = (cnt < 16) ? 1 : 0;
}
__global__ void convert_kernel(const int* __restrict__ raw) {
    int i = blockIdx.x * blockDim.x + threadIdx.x;
    if (i >= NE) return;
    int s, d;
    if (g_is64) {
        const long long* p = (const long long*)raw;
        s = (int)p[i];
        d = (int)p[NE + i];
    } else {
        s = raw[i];
        d = raw[NE + i];
    }
    if ((unsigned)s >= NN) s = 0;
    if ((unsigned)d >= NN) d = 0;
    g_src[i] = s;
    g_dst[i] = d;
}

// ================= weight split prep =================
#define NJOBS 15
struct WJob { const float* src; int Ksrc; int Kpad; int dst; };
struct WJobs { WJob j[NJOBS]; };
__global__ void conv_w_kernel(WJobs jobs) {
    WJob jb = jobs.j[blockIdx.y];
    int idx = blockIdx.x * 256 + threadIdx.x;
    if (idx >= 128 * jb.Kpad) return;
    int n = idx / jb.Kpad, k = idx % jb.Kpad;
    float v = (k < jb.Ksrc) ? jb.src[(size_t)k * 128 + n] : 0.f;
    __half h = __float2half_rn(v);
    float r = v - __half2float(h);
    g_wh[(size_t)jb.dst + (size_t)n * jb.Kpad + k] = h;
    g_wl[(size_t)jb.dst + (size_t)n * jb.Kpad + k] = __float2half_rn(r);
}

// ================= A gather (one 128-row half of the 256-row tile) =================
template <int MODE>
__device__ __forceinline__ void a_load(const float* __restrict__ in0,
                                       const float* __restrict__ in1,
                                       int chunk, int half, int row0, int rows,
                                       int t, float4* v) {
    const int r = (t >> 2) + half * 128;
    const int kh = (t & 3) << 4;          // 0,16,32,48
    const int gk = chunk * 64 + kh;
    const int row = row0 + r;
    const float* src = nullptr;
    if (MODE == 0) {
        if (kh == 0 && row < rows) src = in0 + (size_t)row * 16;
    } else if (MODE == 1) {
        if (row < rows) {
            int sect = gk >> 7;
            int coff = gk & 127;
            if (sect == 0)      src = in0 + (size_t)g_dst[row] * HD + coff;
            else if (sect == 1) src = in0 + (size_t)g_src[row] * HD + coff;
            else                src = in1 + (size_t)row * HD + coff;
        }
    } else {
        if (row < rows) {
            int sect = gk >> 7;
            int coff = gk & 127;
            src = (sect ? in1 : in0) + (size_t)row * HD + coff;
        }
    }
    v[0] = v[1] = v[2] = v[3] = make_float4(0.f, 0.f, 0.f, 0.f);
    if (src) {
        v[0] = *(const float4*)(src);
        v[1] = *(const float4*)(src + 4);
        v[2] = *(const float4*)(src + 8);
        v[3] = *(const float4*)(src + 12);
    }
}

__device__ __forceinline__ void a_store(char* sm, uint32_t slotHi, int half,
                                        int t, const float4* v) {
    const int r = (t >> 2) + half * 128;
    const int kh = (t & 3) << 4;
    const uint32_t rbase = (uint32_t)r * LDT;
#pragma unroll
    for (int g = 0; g < 2; g++) {
        uint32_t h[4], l[4];
        pack_pair(v[2 * g].x,     v[2 * g].y,     h[0], l[0]);
        pack_pair(v[2 * g].z,     v[2 * g].w,     h[1], l[1]);
        pack_pair(v[2 * g + 1].x, v[2 * g + 1].y, h[2], l[2]);
        pack_pair(v[2 * g + 1].z, v[2 * g + 1].w, h[3], l[3]);
        uint32_t off = rbase + (uint32_t)(kh + g * 8) * 2u;
        *(uint4*)(sm + slotHi + off)          = make_uint4(h[0], h[1], h[2], h[3]);
        *(uint4*)(sm + slotHi + A_PAIR + off) = make_uint4(l[0], l[1], l[2], l[3]);
    }
}

// W tile (128 n x 64 k) via cp.async; Kpad may be < 64 (emb L1)
__device__ __forceinline__ void load_w_async(uint32_t sb, uint32_t wb,
                                             int wofs, int kc, int Kpad, int t) {
    const int n = t >> 2;
    const int kh = (t & 3) << 4;
    if (n >= 128) return;
    if (kh >= Kpad) return;
    const __half* ph = g_wh + wofs + (size_t)n * Kpad + kc + kh;
    const __half* pl = g_wl + wofs + (size_t)n * Kpad + kc + kh;
    const uint32_t nb = (uint32_t)n * LDT;
#pragma unroll
    for (int g = 0; g < 2; g++) {
        uint32_t off = nb + (uint32_t)(kh + g * 8) * 2u;
        cp16(sb + wb + off, ph + g * 8);
        cp16(sb + wb + W_PAIR + off, pl + g * 8);
    }
}

// ================= warp MMA: 32(M) x 64(N) tile over one 64-col chunk =================
template <int K16S>
__device__ __forceinline__ void mma_chunk(uint32_t sb, uint32_t aHi, uint32_t wB,
                                          float (&acc)[2][8][4], int m0, int n0, int lane) {
    const uint32_t aLo = aHi + A_PAIR;
    const uint32_t wLo = wB + W_PAIR;
    const int rowA = m0 + (lane & 15);
    const int kselA = (lane >> 4) << 3;
    const uint32_t aB0 = (uint32_t)rowA * LDT;
    const uint32_t aB1 = aB0 + 16u * LDT;
    const int rowB = n0 + (lane & 7) + (((lane >> 4) & 1) << 3);
    const int kselB = ((lane >> 3) & 1) << 3;
#pragma unroll
    for (int ks = 0; ks < K16S; ks++) {
        const int k16 = ks * 16;
        uint32_t ah[2][4], al[2][4];
        uint32_t ak = (uint32_t)(k16 + kselA) * 2u;
        ldsm4(sb + aHi + aB0 + ak, ah[0]);
        ldsm4(sb + aHi + aB1 + ak, ah[1]);
        ldsm4(sb + aLo + aB0 + ak, al[0]);
        ldsm4(sb + aLo + aB1 + ak, al[1]);
        uint32_t bk = (uint32_t)(k16 + kselB) * 2u;
#pragma unroll
        for (int nb = 0; nb < 4; nb++) {
            uint32_t bh[4], bl[4];
            uint32_t bb = (uint32_t)(rowB + nb * 16) * LDT;
            ldsm4(sb + wB + bb + bk, bh);
            ldsm4(sb + wLo + bb + bk, bl);
#pragma unroll
            for (int mi = 0; mi < 2; mi++) {
                mma16816(acc[mi][nb * 2],     ah[mi], bh[0], bh[1]);
                mma16816(acc[mi][nb * 2 + 1], ah[mi], bh[2], bh[3]);
            }
#pragma unroll
            for (int mi = 0; mi < 2; mi++) {
                mma16816(acc[mi][nb * 2],     al[mi], bh[0], bh[1]);
                mma16816(acc[mi][nb * 2 + 1], al[mi], bh[2], bh[3]);
            }
#pragma unroll
            for (int mi = 0; mi < 2; mi++) {
                mma16816(acc[mi][nb * 2],     ah[mi], bl[0], bl[1]);
                mma16816(acc[mi][nb * 2 + 1], ah[mi], bl[2], bl[3]);
            }
        }
    }
}

__device__ __forceinline__ void zero_acc(float (&acc)[2][8][4]) {
#pragma unroll
    for (int mi = 0; mi < 2; mi++)
#pragma unroll
        for (int j = 0; j < 8; j++)
#pragma unroll
            for (int e = 0; e < 4; e++) acc[mi][j][e] = 0.f;
}

// ================= epilogues =================
__device__ __forceinline__ void epi_silu(char* sm, float (&acc)[2][8][4],
                                         const float* __restrict__ bias,
                                         int m0, int n0, int lane) {
    const int cq = (lane & 3) << 1;
    const int r0l = lane >> 2;
#pragma unroll
    for (int mi = 0; mi < 2; mi++)
#pragma unroll
        for (int j = 0; j < 8; j++) {
            int c = n0 + j * 8 + cq;
            float b0 = bias[c], b1 = bias[c + 1];
            uint32_t hiT = SL(c >> 6);
            int hc = c & 63;
#pragma unroll
            for (int h = 0; h < 2; h++) {
                float v0 = silu(acc[mi][j][2 * h] + b0);
                float v1 = silu(acc[mi][j][2 * h + 1] + b1);
                uint32_t hi, lo;
                pack_pair(v0, v1, hi, lo);
                int r = m0 + mi * 16 + r0l + 8 * h;
                uint32_t off = (uint32_t)r * LDT + (uint32_t)(hc * 2);
                *(uint32_t*)(sm + hiT + off)          = hi;
                *(uint32_t*)(sm + hiT + A_PAIR + off) = lo;
            }
        }
}

__device__ __forceinline__ void epi_ln(char* sm, float (&acc)[2][8][4],
                                       const float* __restrict__ bias,
                                       const float* __restrict__ gam,
                                       const float* __restrict__ bet,
                                       float (*sRed)[ROWS_CTA][2],
                                       int m0, int n0, int wn, int lane) {
    const int cq = (lane & 3) << 1;
    const int r0l = lane >> 2;
    float s[2][2] = {{0.f, 0.f}, {0.f, 0.f}};
    float q[2][2] = {{0.f, 0.f}, {0.f, 0.f}};
#pragma unroll
    for (int mi = 0; mi < 2; mi++)
#pragma unroll
        for (int j = 0; j < 8; j++) {
            int c = n0 + j * 8 + cq;
            float b0 = bias[c], b1 = bias[c + 1];
#pragma unroll
            for (int h = 0; h < 2; h++) {
                float v0 = acc[mi][j][2 * h] + b0;
                float v1 = acc[mi][j][2 * h + 1] + b1;
                s[mi][h] += v0 + v1;
                q[mi][h] += v0 * v0 + v1 * v1;
            }
        }
#pragma unroll
    for (int o = 1; o <= 2; o <<= 1)
#pragma unroll
        for (int mi = 0; mi < 2; mi++)
#pragma unroll
            for (int h = 0; h < 2; h++) {
                s[mi][h] += __shfl_xor_sync(0xffffffffu, s[mi][h], o);
                q[mi][h] += __shfl_xor_sync(0xffffffffu, q[mi][h], o);
            }
    if ((lane & 3) == 0) {
#pragma unroll
        for (int mi = 0; mi < 2; mi++)
#pragma unroll
            for (int h = 0; h < 2; h++) {
                int r = m0 + mi * 16 + r0l + 8 * h;
                sRed[wn][r][0] = s[mi][h];
                sRed[wn][r][1] = q[mi][h];
            }
    }
    __syncthreads();
    float mu[2][2], rs[2][2];
#pragma unroll
    for (int mi = 0; mi < 2; mi++)
#pragma unroll
        for (int h = 0; h < 2; h++) {
            int r = m0 + mi * 16 + r0l + 8 * h;
            float S = sRed[0][r][0] + sRed[1][r][0];
            float Q = sRed[0][r][1] + sRed[1][r][1];
            float m = S * (1.f / HD);
            float var = Q * (1.f / HD) - m * m;
            mu[mi][h] = m;
            rs[mi][h] = rsqrtf(var + LN_EPS);
        }
    float* so = (float*)(sm + 73728u);
#pragma unroll
    for (int mi = 0; mi < 2; mi++)
#pragma unroll
        for (int j = 0; j < 8; j++) {
            int c = n0 + j * 8 + cq;
            float b0 = bias[c], b1 = bias[c + 1];
            float g0 = gam[c], g1 = gam[c + 1];
            float e0 = bet[c], e1 = bet[c + 1];
#pragma unroll
            for (int h = 0; h < 2; h++) {
                int r = m0 + mi * 16 + r0l + 8 * h;
                float v0 = acc[mi][j][2 * h] + b0;
                float v1 = acc[mi][j][2 * h + 1] + b1;
                so[r * 130 + c]     = (v0 - mu[mi][h]) * rs[mi][h] * g0 + e0;
                so[r * 130 + c + 1] = (v1 - mu[mi][h]) * rs[mi][h] * g1 + e1;
            }
        }
}

// ================= fused MLP kernel (512 threads, M=256, pipelined) =================
// SCAT: also red.add the final row into g_agg[dst[row]] (edge kernels)
template <int MODE, int NCH, int K16S1, int SCAT>
__global__ __launch_bounds__(512, 1) void mma_mlp(
    const float* __restrict__ in0, const float* __restrict__ in1,
    int o1, int o2, int o3, int Kpad1,
    const float* __restrict__ b1, const float* __restrict__ b2,
    const float* __restrict__ b3, const float* __restrict__ gam,
    const float* __restrict__ bet,
    const float* __restrict__ resid, float* __restrict__ out, int rows) {
    extern __shared__ char sm[];
    __shared__ float sRed[2][ROWS_CTA][2];
    const int t = threadIdx.x;
    const uint32_t sb = smem_u32(sm);
    const int lane = t & 31, w = t >> 5;
    const int m0 = (w & 7) * 32, n0 = (w >> 3) * 64, wn = w >> 3;
    const int row0 = blockIdx.x * ROWS_CTA;
    float acc[2][8][4];
    float4 v[4];

    // ---- layer 1: pipelined 64-col chunks ----
    zero_acc(acc);
    for (int c = 0; c < NCH; c++) {
        __syncthreads();                         // SL(c&1), WB(c&1) free
        a_load<MODE>(in0, in1, c, 0, row0, rows, t, v);
        a_store((char*)sm, SL(c & 1), 0, t, v);
        a_load<MODE>(in0, in1, c, 1, row0, rows, t, v);
        a_store((char*)sm, SL(c & 1), 1, t, v);
        load_w_async(sb, WB(c & 1), o1, c * 64, Kpad1, t);
        CP_COMMIT();
        if (c > 0) mma_chunk<K16S1>(sb, SL((c - 1) & 1), WB((c - 1) & 1), acc, m0, n0, lane);
        CP_WAIT0();
    }
    __syncthreads();
    mma_chunk<K16S1>(sb, SL((NCH - 1) & 1), WB((NCH - 1) & 1), acc, m0, n0, lane);
    __syncthreads();

    // ---- layer 2 ----
    load_w_async(sb, WB(0), o2, 0, 128, t);
    load_w_async(sb, WB(1), o2, 64, 128, t);
    CP_COMMIT();
    epi_silu((char*)sm, acc, b1, m0, n0, lane);
    zero_acc(acc);
    CP_WAIT0();
    __syncthreads();
    mma_chunk<4>(sb, SL(0), WB(0), acc, m0, n0, lane);
    mma_chunk<4>(sb, SL(1), WB(1), acc, m0, n0, lane);
    __syncthreads();

    // ---- layer 3 ----
    load_w_async(sb, WB(0), o3, 0, 128, t);
    load_w_async(sb, WB(1), o3, 64, 128, t);
    CP_COMMIT();
    epi_silu((char*)sm, acc, b2, m0, n0, lane);
    zero_acc(acc);
    CP_WAIT0();
    __syncthreads();
    mma_chunk<4>(sb, SL(0), WB(0), acc, m0, n0, lane);
    mma_chunk<4>(sb, SL(1), WB(1), acc, m0, n0, lane);
    __syncthreads();
    epi_ln((char*)sm, acc, b3, gam, bet, sRed, m0, n0, wn, lane);
    __syncthreads();

    // ---- residual + vectorized store (+ fused segment-sum scatter) ----
    // warp w handles rows w, w+16, ...; lanes cover 128 cols as float4.
    const float* so = (const float*)(sm + 73728u);
    const int c4 = lane << 2;
    for (int r = w; r < ROWS_CTA; r += 16) {
        int row = row0 + r;
        if (row < rows) {
            const float* sr = so + r * 130 + c4;
            float4 y = make_float4(sr[0], sr[1], sr[2], sr[3]);
            if (MODE != 0) {
                float4 rv = *(const float4*)(resid + (size_t)row * HD + c4);
                y.x += rv.x; y.y += rv.y; y.z += rv.z; y.w += rv.w;
            }
            *(float4*)(out + (size_t)row * HD + c4) = y;
            if (SCAT) {
                float* p = g_agg + (size_t)g_dst[row] * HD + c4;
                asm volatile("red.global.add.v4.f32 [%0], {%1, %2, %3, %4};"
                             :: "l"(p), "f"(y.x), "f"(y.y), "f"(y.z), "f"(y.w)
                             : "memory");
            }
        }
    }
}

// ================= aggregation buffer zero =================
__global__ void zero_agg_kernel() {
    size_t i = (size_t)blockIdx.x * blockDim.x + threadIdx.x;
    if (i < (size_t)NN * HD) g_agg[i] = 0.f;
}

// ================= launch =================
extern "C" void kernel_launch(void* const* d_in, const int* in_sizes, int n_in,
                              void* d_out, int out_size) {
    const float* x_in    = (const float*)d_in[0];
    const int*   eidx    = (const int*)d_in[1];
    const float* eattr   = (const float*)d_in[2];
    const float* emb_W1  = (const float*)d_in[3];
    const float* emb_b1  = (const float*)d_in[4];
    const float* emb_W2  = (const float*)d_in[5];
    const float* emb_b2  = (const float*)d_in[6];
    const float* emb_W3  = (const float*)d_in[7];
    const float* emb_b3  = (const float*)d_in[8];
    const float* emb_g   = (const float*)d_in[9];
    const float* emb_be  = (const float*)d_in[10];
    const float* edge_W1 = (const float*)d_in[11];
    const float* edge_b1 = (const float*)d_in[12];
    const float* edge_W2 = (const float*)d_in[13];
    const float* edge_b2 = (const float*)d_in[14];
    const float* edge_W3 = (const float*)d_in[15];
    const float* edge_b3 = (const float*)d_in[16];
    const float* edge_g  = (const float*)d_in[17];
    const float* edge_be = (const float*)d_in[18];
    const float* node_W1 = (const float*)d_in[19];
    const float* node_b1 = (const float*)d_in[20];
    const float* node_W2 = (const float*)d_in[21];
    const float* node_b2 = (const float*)d_in[22];
    const float* node_W3 = (const float*)d_in[23];
    const float* node_b3 = (const float*)d_in[24];
    const float* node_g  = (const float*)d_in[25];
    const float* node_be = (const float*)d_in[26];

    float* out_x = (float*)d_out;
    float* out_e = (float*)d_out + (size_t)NN * HD;

    float *eA, *eB, *agg, *xbuf;
    cudaGetSymbolAddress((void**)&eA, g_eA);
    cudaGetSymbolAddress((void**)&eB, g_eB);
    cudaGetSymbolAddress((void**)&agg, g_agg);
    cudaGetSymbolAddress((void**)&xbuf, g_x);

    cudaFuncSetAttribute((const void*)mma_mlp<0, 1, 1, 0>, cudaFuncAttributeMaxDynamicSharedMemorySize, SMEM_DYN);
    cudaFuncSetAttribute((const void*)mma_mlp<1, 6, 4, 1>, cudaFuncAttributeMaxDynamicSharedMemorySize, SMEM_DYN);
    cudaFuncSetAttribute((const void*)mma_mlp<2, 4, 4, 0>, cudaFuncAttributeMaxDynamicSharedMemorySize, SMEM_DYN);

    // index prep (clamped)
    detect_kernel<<<1, 256>>>(eidx);
    convert_kernel<<<(NE + 255) / 256, 256>>>(eidx);

    // pool offsets (elements)
    const int oEmb1 = 0, oEmb2 = 8192, oEmb3 = 24576;
    int oE1[2], oE2[2], oE3[2], oN1[2], oN2[2], oN3[2];
    int base = 40960;
    for (int l = 0; l < 2; l++) {
        oE1[l] = base;
        oE2[l] = base + 49152;
        oE3[l] = base + 65536;
        oN1[l] = base + 81920;
        oN2[l] = base + 114688;
        oN3[l] = base + 131072;
        base += 147456;
    }

    WJobs jobs;
    int ji = 0;
    jobs.j[ji++] = {emb_W1, 16, 16, oEmb1};
    jobs.j[ji++] = {emb_W2, 128, 128, oEmb2};
    jobs.j[ji++] = {emb_W3, 128, 128, oEmb3};
    for (int l = 0; l < 2; l++) {
        jobs.j[ji++] = {edge_W1 + (size_t)l * 3 * HD * HD, 384, 384, oE1[l]};
        jobs.j[ji++] = {edge_W2 + (size_t)l * HD * HD, 128, 128, oE2[l]};
        jobs.j[ji++] = {edge_W3 + (size_t)l * HD * HD, 128, 128, oE3[l]};
        jobs.j[ji++] = {node_W1 + (size_t)l * 2 * HD * HD, 256, 256, oN1[l]};
        jobs.j[ji++] = {node_W2 + (size_t)l * HD * HD, 128, 128, oN2[l]};
        jobs.j[ji++] = {node_W3 + (size_t)l * HD * HD, 128, 128, oN3[l]};
    }
    dim3 cg((128 * 384 + 255) / 256, NJOBS);
    conv_w_kernel<<<cg, 256>>>(jobs);

    const int edge_blocks = (NE + ROWS_CTA - 1) / ROWS_CTA;   // 1563
    const int node_blocks = (NN + ROWS_CTA - 1) / ROWS_CTA;   // 98
    const int nthr_blocks = (int)(((size_t)NN * HD + 255) / 256);

    // edge embedding: e = MLP(edge_attr)
    mma_mlp<0, 1, 1, 0><<<edge_blocks, 512, SMEM_DYN>>>(
        eattr, nullptr, oEmb1, oEmb2, oEmb3, 16,
        emb_b1, emb_b2, emb_b3, emb_g, emb_be, nullptr, eA, NE);

    const float* x_cur = x_in;
    float* e_cur = eA;
    for (int l = 0; l < 2; l++) {
        float* e_out = (l == 0) ? eB : out_e;
        float* x_out = (l == 0) ? xbuf : out_x;

        // agg must be zero before the fused scatter in the edge MLP
        zero_agg_kernel<<<nthr_blocks, 256>>>();

        // e_new = MLP([x[dst] | x[src] | e]) + e ; agg += e_new (fused scatter)
        mma_mlp<1, 6, 4, 1><<<edge_blocks, 512, SMEM_DYN>>>(
            x_cur, e_cur, oE1[l], oE2[l], oE3[l], 384,
            edge_b1 + l * HD, edge_b2 + l * HD, edge_b3 + l * HD,
            edge_g + l * HD, edge_be + l * HD, e_cur, e_out, NE);

        // x = MLP([x | agg]) + x
        mma_mlp<2, 4, 4, 0><<<node_blocks, 512, SMEM_DYN>>>(
            x_cur, agg, oN1[l], oN2[l], oN3[l], 256,
            node_b1 + l * HD, node_b2 + l * HD, node_b3 + l * HD,
            node_g + l * HD, node_be + l * HD, x_cur, x_out, NN);

        e_cur = e_out;
        x_cur = x_out;
    }
}

// round 15
// speedup vs baseline: 1.2907x; 1.2404x over previous
#include <cuda_runtime.h>
#include <cuda_fp16.h>
#include <cstdint>

#define NN 25000
#define NE 400000
#define HD 128
#define LN_EPS 1e-5f

// ================= device scratch =================
__device__ int   g_src[NE];
__device__ int   g_dst[NE];
__device__ int   g_is64;
__device__ float g_eA[(size_t)NE * HD];
__device__ float g_eB[(size_t)NE * HD];
__device__ float g_agg[(size_t)NN * HD];
__device__ float g_x[(size_t)NN * HD];

// fp16 hi/lo weight pools, [n=128][Kpad] row-major per matrix
// (W = wh + wl is exact to ~2^-22; all compensation lives on the W side)
#define POOL_ELEMS 335872
__device__ __align__(16) __half g_wh[POOL_ELEMS];
__device__ __align__(16) __half g_wl[POOL_ELEMS];

// ================= smem layout (dynamic, bytes) =================
// M=256 rows per CTA. 64-col tiles, row stride 144 B.
// W tile pair (hi+lo, 128 n-rows): 36864 B. Double buffer WB(0), WB(1) in [0,73728).
// A/H slot (hi only, 256 rows): 36864 B. SL(0), SL(1) in [73728, 147456).
#define LDT      144u
#define WB(i)    ((uint32_t)(i) * 36864u)
#define SL(i)    (73728u + (uint32_t)(i) * 36864u)
#define W_PAIR   18432u
#define SMEM_DYN 147456
#define ROWS_CTA 256
// f32 LN staging: floats at byte 0 (W+A fully consumed by then), stride 130
// (256*130*4 = 133120 B <= 147456)

// ================= helpers =================
__device__ __forceinline__ uint32_t smem_u32(const void* p) {
    uint32_t a;
    asm("{ .reg .u64 t; cvta.to.shared.u64 t, %1; cvt.u32.u64 %0, t; }"
        : "=r"(a) : "l"(p));
    return a;
}
__device__ __forceinline__ void ldsm4(uint32_t addr, uint32_t* r) {
    asm volatile("ldmatrix.sync.aligned.m8n8.x4.shared.b16 {%0,%1,%2,%3}, [%4];"
                 : "=r"(r[0]), "=r"(r[1]), "=r"(r[2]), "=r"(r[3]) : "r"(addr));
}
__device__ __forceinline__ void mma16816(float* d, const uint32_t* a,
                                         uint32_t b0, uint32_t b1) {
    asm("mma.sync.aligned.m16n8k16.row.col.f32.f16.f16.f32 "
        "{%0,%1,%2,%3}, {%4,%5,%6,%7}, {%8,%9}, {%0,%1,%2,%3};"
        : "+f"(d[0]), "+f"(d[1]), "+f"(d[2]), "+f"(d[3])
        : "r"(a[0]), "r"(a[1]), "r"(a[2]), "r"(a[3]), "r"(b0), "r"(b1));
}
__device__ __forceinline__ void cp16(uint32_t dst, const void* src) {
    asm volatile("cp.async.cg.shared.global [%0], [%1], 16;"
                 :: "r"(dst), "l"(src));
}
#define CP_COMMIT() asm volatile("cp.async.commit_group;")
#define CP_WAIT0()  asm volatile("cp.async.wait_group 0;" ::: "memory")
__device__ __forceinline__ uint32_t pack2(float a, float b) {
    __half2 H = __floats2half2_rn(a, b);
    return *reinterpret_cast<uint32_t*>(&H);
}
__device__ __forceinline__ float silu(float v) {
    return __fdividef(v, 1.f + __expf(-v));
}

// ================= index prep =================
__global__ void detect_kernel(const int* __restrict__ raw) {
    __shared__ int cnt;
    if (threadIdx.x == 0) cnt = 0;
    __syncthreads();
    int c = 0;
    for (int t = threadIdx.x; t < 1024; t += blockDim.x)
        if (raw[2 * t + 1] != 0) c++;
    atomicAdd(&cnt, c);
    __syncthreads();
    if (threadIdx.x == 0) g_is64 = (cnt < 16) ? 1 : 0;
}
__global__ void convert_kernel(const int* __restrict__ raw) {
    int i = blockIdx.x * blockDim.x + threadIdx.x;
    if (i >= NE) return;
    int s, d;
    if (g_is64) {
        const long long* p = (const long long*)raw;
        s = (int)p[i];
        d = (int)p[NE + i];
    } else {
        s = raw[i];
        d = raw[NE + i];
    }
    if ((unsigned)s >= NN) s = 0;
    if ((unsigned)d >= NN) d = 0;
    g_src[i] = s;
    g_dst[i] = d;
}

// ================= weight split prep =================
#define NJOBS 15
struct WJob { const float* src; int Ksrc; int Kpad; int dst; };
struct WJobs { WJob j[NJOBS]; };
__global__ void conv_w_kernel(WJobs jobs) {
    WJob jb = jobs.j[blockIdx.y];
    int idx = blockIdx.x * 256 + threadIdx.x;
    if (idx >= 128 * jb.Kpad) return;
    int n = idx / jb.Kpad, k = idx % jb.Kpad;
    float v = (k < jb.Ksrc) ? jb.src[(size_t)k * 128 + n] : 0.f;
    __half h = __float2half_rn(v);
    float r = v - __half2float(h);
    g_wh[(size_t)jb.dst + (size_t)n * jb.Kpad + k] = h;
    g_wl[(size_t)jb.dst + (size_t)n * jb.Kpad + k] = __float2half_rn(r);
}

// ================= A gather (one 128-row half of the 256-row tile) =================
template <int MODE>
__device__ __forceinline__ void a_load(const float* __restrict__ in0,
                                       const float* __restrict__ in1,
                                       int chunk, int half, int row0, int rows,
                                       int t, float4* v) {
    const int r = (t >> 2) + half * 128;
    const int kh = (t & 3) << 4;          // 0,16,32,48
    const int gk = chunk * 64 + kh;
    const int row = row0 + r;
    const float* src = nullptr;
    if (MODE == 0) {
        if (kh == 0 && row < rows) src = in0 + (size_t)row * 16;
    } else if (MODE == 1) {
        if (row < rows) {
            int sect = gk >> 7;
            int coff = gk & 127;
            if (sect == 0)      src = in0 + (size_t)g_dst[row] * HD + coff;
            else if (sect == 1) src = in0 + (size_t)g_src[row] * HD + coff;
            else                src = in1 + (size_t)row * HD + coff;
        }
    } else {
        if (row < rows) {
            int sect = gk >> 7;
            int coff = gk & 127;
            src = (sect ? in1 : in0) + (size_t)row * HD + coff;
        }
    }
    v[0] = v[1] = v[2] = v[3] = make_float4(0.f, 0.f, 0.f, 0.f);
    if (src) {
        v[0] = *(const float4*)(src);
        v[1] = *(const float4*)(src + 4);
        v[2] = *(const float4*)(src + 8);
        v[3] = *(const float4*)(src + 12);
    }
}

// pack fp16 (hi only) and store
__device__ __forceinline__ void a_store(char* sm, uint32_t slot, int half,
                                        int t, const float4* v) {
    const int r = (t >> 2) + half * 128;
    const int kh = (t & 3) << 4;
    const uint32_t rbase = (uint32_t)r * LDT;
#pragma unroll
    for (int g = 0; g < 2; g++) {
        uint4 h;
        h.x = pack2(v[2 * g].x,     v[2 * g].y);
        h.y = pack2(v[2 * g].z,     v[2 * g].w);
        h.z = pack2(v[2 * g + 1].x, v[2 * g + 1].y);
        h.w = pack2(v[2 * g + 1].z, v[2 * g + 1].w);
        uint32_t off = rbase + (uint32_t)(kh + g * 8) * 2u;
        *(uint4*)(sm + slot + off) = h;
    }
}

// W tile (128 n x 64 k, hi+lo) via cp.async; Kpad may be < 64 (emb L1)
__device__ __forceinline__ void load_w_async(uint32_t sb, uint32_t wb,
                                             int wofs, int kc, int Kpad, int t) {
    const int n = t >> 2;
    const int kh = (t & 3) << 4;
    if (kh >= Kpad) return;
    const __half* ph = g_wh + wofs + (size_t)n * Kpad + kc + kh;
    const __half* pl = g_wl + wofs + (size_t)n * Kpad + kc + kh;
    const uint32_t nb = (uint32_t)n * LDT;
#pragma unroll
    for (int g = 0; g < 2; g++) {
        uint32_t off = nb + (uint32_t)(kh + g * 8) * 2u;
        cp16(sb + wb + off, ph + g * 8);
        cp16(sb + wb + W_PAIR + off, pl + g * 8);
    }
}

// ================= warp MMA: 32(M) x 64(N) over one 64-col chunk, 2 passes =========
template <int K16S>
__device__ __forceinline__ void mma_chunk(uint32_t sb, uint32_t aB, uint32_t wB,
                                          float (&acc)[2][8][4], int m0, int n0, int lane) {
    const uint32_t wLo = wB + W_PAIR;
    const int rowA = m0 + (lane & 15);
    const int kselA = (lane >> 4) << 3;
    const uint32_t aB0 = (uint32_t)rowA * LDT;
    const uint32_t aB1 = aB0 + 16u * LDT;
    const int rowB = n0 + (lane & 7) + (((lane >> 4) & 1) << 3);
    const int kselB = ((lane >> 3) & 1) << 3;
#pragma unroll
    for (int ks = 0; ks < K16S; ks++) {
        const int k16 = ks * 16;
        uint32_t ah[2][4];
        uint32_t ak = (uint32_t)(k16 + kselA) * 2u;
        ldsm4(sb + aB + aB0 + ak, ah[0]);
        ldsm4(sb + aB + aB1 + ak, ah[1]);
        uint32_t bk = (uint32_t)(k16 + kselB) * 2u;
#pragma unroll
        for (int nb = 0; nb < 4; nb++) {
            uint32_t bh[4], bl[4];
            uint32_t bb = (uint32_t)(rowB + nb * 16) * LDT;
            ldsm4(sb + wB + bb + bk, bh);
            ldsm4(sb + wLo + bb + bk, bl);
            // pass 1: Ah x Wh
#pragma unroll
            for (int mi = 0; mi < 2; mi++) {
                mma16816(acc[mi][nb * 2],     ah[mi], bh[0], bh[1]);
                mma16816(acc[mi][nb * 2 + 1], ah[mi], bh[2], bh[3]);
            }
            // pass 2: Ah x Wl
#pragma unroll
            for (int mi = 0; mi < 2; mi++) {
                mma16816(acc[mi][nb * 2],     ah[mi], bl[0], bl[1]);
                mma16816(acc[mi][nb * 2 + 1], ah[mi], bl[2], bl[3]);
            }
        }
    }
}

__device__ __forceinline__ void zero_acc(float (&acc)[2][8][4]) {
#pragma unroll
    for (int mi = 0; mi < 2; mi++)
#pragma unroll
        for (int j = 0; j < 8; j++)
#pragma unroll
            for (int e = 0; e < 4; e++) acc[mi][j][e] = 0.f;
}

// ================= epilogues =================
// SiLU -> H slots (hi only): cols 0-63 -> SL(0), 64-127 -> SL(1)
__device__ __forceinline__ void epi_silu(char* sm, float (&acc)[2][8][4],
                                         const float* __restrict__ bias,
                                         int m0, int n0, int lane) {
    const int cq = (lane & 3) << 1;
    const int r0l = lane >> 2;
#pragma unroll
    for (int mi = 0; mi < 2; mi++)
#pragma unroll
        for (int j = 0; j < 8; j++) {
            int c = n0 + j * 8 + cq;
            float b0 = bias[c], b1 = bias[c + 1];
            uint32_t hiT = SL(c >> 6);
            int hc = c & 63;
#pragma unroll
            for (int h = 0; h < 2; h++) {
                float v0 = silu(acc[mi][j][2 * h] + b0);
                float v1 = silu(acc[mi][j][2 * h + 1] + b1);
                int r = m0 + mi * 16 + r0l + 8 * h;
                uint32_t off = (uint32_t)r * LDT + (uint32_t)(hc * 2);
                *(uint32_t*)(sm + hiT + off) = pack2(v0, v1);
            }
        }
}

__device__ __forceinline__ void epi_ln(char* sm, float (&acc)[2][8][4],
                                       const float* __restrict__ bias,
                                       const float* __restrict__ gam,
                                       const float* __restrict__ bet,
                                       float (*sRed)[ROWS_CTA][2],
                                       int m0, int n0, int wn, int lane) {
    const int cq = (lane & 3) << 1;
    const int r0l = lane >> 2;
    float s[2][2] = {{0.f, 0.f}, {0.f, 0.f}};
    float q[2][2] = {{0.f, 0.f}, {0.f, 0.f}};
#pragma unroll
    for (int mi = 0; mi < 2; mi++)
#pragma unroll
        for (int j = 0; j < 8; j++) {
            int c = n0 + j * 8 + cq;
            float b0 = bias[c], b1 = bias[c + 1];
#pragma unroll
            for (int h = 0; h < 2; h++) {
                float v0 = acc[mi][j][2 * h] + b0;
                float v1 = acc[mi][j][2 * h + 1] + b1;
                s[mi][h] += v0 + v1;
                q[mi][h] += v0 * v0 + v1 * v1;
            }
        }
#pragma unroll
    for (int o = 1; o <= 2; o <<= 1)
#pragma unroll
        for (int mi = 0; mi < 2; mi++)
#pragma unroll
            for (int h = 0; h < 2; h++) {
                s[mi][h] += __shfl_xor_sync(0xffffffffu, s[mi][h], o);
                q[mi][h] += __shfl_xor_sync(0xffffffffu, q[mi][h], o);
            }
    if ((lane & 3) == 0) {
#pragma unroll
        for (int mi = 0; mi < 2; mi++)
#pragma unroll
            for (int h = 0; h < 2; h++) {
                int r = m0 + mi * 16 + r0l + 8 * h;
                sRed[wn][r][0] = s[mi][h];
                sRed[wn][r][1] = q[mi][h];
            }
    }
    __syncthreads();
    float mu[2][2], rs[2][2];
#pragma unroll
    for (int mi = 0; mi < 2; mi++)
#pragma unroll
        for (int h = 0; h < 2; h++) {
            int r = m0 + mi * 16 + r0l + 8 * h;
            float S = sRed[0][r][0] + sRed[1][r][0];
            float Q = sRed[0][r][1] + sRed[1][r][1];
            float m = S * (1.f / HD);
            float var = Q * (1.f / HD) - m * m;
            mu[mi][h] = m;
            rs[mi][h] = rsqrtf(var + LN_EPS);
        }
    float* so = (float*)sm;   // staging at offset 0 (W + A consumed)
#pragma unroll
    for (int mi = 0; mi < 2; mi++)
#pragma unroll
        for (int j = 0; j < 8; j++) {
            int c = n0 + j * 8 + cq;
            float b0 = bias[c], b1 = bias[c + 1];
            float g0 = gam[c], g1 = gam[c + 1];
            float e0 = bet[c], e1 = bet[c + 1];
#pragma unroll
            for (int h = 0; h < 2; h++) {
                int r = m0 + mi * 16 + r0l + 8 * h;
                float v0 = acc[mi][j][2 * h] + b0;
                float v1 = acc[mi][j][2 * h + 1] + b1;
                so[r * 130 + c]     = (v0 - mu[mi][h]) * rs[mi][h] * g0 + e0;
                so[r * 130 + c + 1] = (v1 - mu[mi][h]) * rs[mi][h] * g1 + e1;
            }
        }
}

// ================= fused MLP kernel (512 threads, M=256, pipelined) =================
// SCAT: also red.add the final row into g_agg[dst[row]] (edge kernels)
template <int MODE, int NCH, int K16S1, int SCAT>
__global__ __launch_bounds__(512, 1) void mma_mlp(
    const float* __restrict__ in0, const float* __restrict__ in1,
    int o1, int o2, int o3, int Kpad1,
    const float* __restrict__ b1, const float* __restrict__ b2,
    const float* __restrict__ b3, const float* __restrict__ gam,
    const float* __restrict__ bet,
    const float* __restrict__ resid, float* __restrict__ out, int rows) {
    extern __shared__ char sm[];
    __shared__ float sRed[2][ROWS_CTA][2];
    const int t = threadIdx.x;
    const uint32_t sb = smem_u32(sm);
    const int lane = t & 31, w = t >> 5;
    const int m0 = (w & 7) * 32, n0 = (w >> 3) * 64, wn = w >> 3;
    const int row0 = blockIdx.x * ROWS_CTA;
    float acc[2][8][4];
    float4 v[4];

    // ---- layer 1: pipelined 64-col chunks ----
    zero_acc(acc);
    for (int c = 0; c < NCH; c++) {
        __syncthreads();                         // SL(c&1), WB(c&1) free
        a_load<MODE>(in0, in1, c, 0, row0, rows, t, v);
        a_store((char*)sm, SL(c & 1), 0, t, v);
        a_load<MODE>(in0, in1, c, 1, row0, rows, t, v);
        a_store((char*)sm, SL(c & 1), 1, t, v);
        load_w_async(sb, WB(c & 1), o1, c * 64, Kpad1, t);
        CP_COMMIT();
        if (c > 0) mma_chunk<K16S1>(sb, SL((c - 1) & 1), WB((c - 1) & 1), acc, m0, n0, lane);
        CP_WAIT0();
    }
    __syncthreads();
    mma_chunk<K16S1>(sb, SL((NCH - 1) & 1), WB((NCH - 1) & 1), acc, m0, n0, lane);
    __syncthreads();

    // ---- layer 2 ----
    load_w_async(sb, WB(0), o2, 0, 128, t);
    load_w_async(sb, WB(1), o2, 64, 128, t);
    CP_COMMIT();
    epi_silu((char*)sm, acc, b1, m0, n0, lane);
    zero_acc(acc);
    CP_WAIT0();
    __syncthreads();
    mma_chunk<4>(sb, SL(0), WB(0), acc, m0, n0, lane);
    mma_chunk<4>(sb, SL(1), WB(1), acc, m0, n0, lane);
    __syncthreads();

    // ---- layer 3 ----
    load_w_async(sb, WB(0), o3, 0, 128, t);
    load_w_async(sb, WB(1), o3, 64, 128, t);
    CP_COMMIT();
    epi_silu((char*)sm, acc, b2, m0, n0, lane);
    zero_acc(acc);
    CP_WAIT0();
    __syncthreads();
    mma_chunk<4>(sb, SL(0), WB(0), acc, m0, n0, lane);
    mma_chunk<4>(sb, SL(1), WB(1), acc, m0, n0, lane);
    __syncthreads();
    epi_ln((char*)sm, acc, b3, gam, bet, sRed, m0, n0, wn, lane);
    __syncthreads();

    // ---- residual + vectorized store (+ fused segment-sum scatter) ----
    const float* so = (const float*)sm;
    const int c4 = lane << 2;
    for (int r = w; r < ROWS_CTA; r += 16) {
        int row = row0 + r;
        if (row < rows) {
            const float* sr = so + r * 130 + c4;
            float4 y = make_float4(sr[0], sr[1], sr[2], sr[3]);
            if (MODE != 0) {
                float4 rv = *(const float4*)(resid + (size_t)row * HD + c4);
                y.x += rv.x; y.y += rv.y; y.z += rv.z; y.w += rv.w;
            }
            *(float4*)(out + (size_t)row * HD + c4) = y;
            if (SCAT) {
                float* p = g_agg + (size_t)g_dst[row] * HD + c4;
                asm volatile("red.global.add.v4.f32 [%0], {%1, %2, %3, %4};"
                             :: "l"(p), "f"(y.x), "f"(y.y), "f"(y.z), "f"(y.w)
                             : "memory");
            }
        }
    }
}

// ================= aggregation buffer zero =================
__global__ void zero_agg_kernel() {
    size_t i = (size_t)blockIdx.x * blockDim.x + threadIdx.x;
    if (i < (size_t)NN * HD) g_agg[i] = 0.f;
}

// ================= launch =================
extern "C" void kernel_launch(void* const* d_in, const int* in_sizes, int n_in,
                              void* d_out, int out_size) {
    const float* x_in    = (const float*)d_in[0];
    const int*   eidx    = (const int*)d_in[1];
    const float* eattr   = (const float*)d_in[2];
    const float* emb_W1  = (const float*)d_in[3];
    const float* emb_b1  = (const float*)d_in[4];
    const float* emb_W2  = (const float*)d_in[5];
    const float* emb_b2  = (const float*)d_in[6];
    const float* emb_W3  = (const float*)d_in[7];
    const float* emb_b3  = (const float*)d_in[8];
    const float* emb_g   = (const float*)d_in[9];
    const float* emb_be  = (const float*)d_in[10];
    const float* edge_W1 = (const float*)d_in[11];
    const float* edge_b1 = (const float*)d_in[12];
    const float* edge_W2 = (const float*)d_in[13];
    const float* edge_b2 = (const float*)d_in[14];
    const float* edge_W3 = (const float*)d_in[15];
    const float* edge_b3 = (const float*)d_in[16];
    const float* edge_g  = (const float*)d_in[17];
    const float* edge_be = (const float*)d_in[18];
    const float* node_W1 = (const float*)d_in[19];
    const float* node_b1 = (const float*)d_in[20];
    const float* node_W2 = (const float*)d_in[21];
    const float* node_b2 = (const float*)d_in[22];
    const float* node_W3 = (const float*)d_in[23];
    const float* node_b3 = (const float*)d_in[24];
    const float* node_g  = (const float*)d_in[25];
    const float* node_be = (const float*)d_in[26];

    float* out_x = (float*)d_out;
    float* out_e = (float*)d_out + (size_t)NN * HD;

    float *eA, *eB, *agg, *xbuf;
    cudaGetSymbolAddress((void**)&eA, g_eA);
    cudaGetSymbolAddress((void**)&eB, g_eB);
    cudaGetSymbolAddress((void**)&agg, g_agg);
    cudaGetSymbolAddress((void**)&xbuf, g_x);

    cudaFuncSetAttribute((const void*)mma_mlp<0, 1, 1, 0>, cudaFuncAttributeMaxDynamicSharedMemorySize, SMEM_DYN);
    cudaFuncSetAttribute((const void*)mma_mlp<1, 6, 4, 1>, cudaFuncAttributeMaxDynamicSharedMemorySize, SMEM_DYN);
    cudaFuncSetAttribute((const void*)mma_mlp<2, 4, 4, 0>, cudaFuncAttributeMaxDynamicSharedMemorySize, SMEM_DYN);

    // index prep (clamped)
    detect_kernel<<<1, 256>>>(eidx);
    convert_kernel<<<(NE + 255) / 256, 256>>>(eidx);

    // pool offsets (elements)
    const int oEmb1 = 0, oEmb2 = 8192, oEmb3 = 24576;
    int oE1[2], oE2[2], oE3[2], oN1[2], oN2[2], oN3[2];
    int base = 40960;
    for (int l = 0; l < 2; l++) {
        oE1[l] = base;
        oE2[l] = base + 49152;
        oE3[l] = base + 65536;
        oN1[l] = base + 81920;
        oN2[l] = base + 114688;
        oN3[l] = base + 131072;
        base += 147456;
    }

    WJobs jobs;
    int ji = 0;
    jobs.j[ji++] = {emb_W1, 16, 16, oEmb1};
    jobs.j[ji++] = {emb_W2, 128, 128, oEmb2};
    jobs.j[ji++] = {emb_W3, 128, 128, oEmb3};
    for (int l = 0; l < 2; l++) {
        jobs.j[ji++] = {edge_W1 + (size_t)l * 3 * HD * HD, 384, 384, oE1[l]};
        jobs.j[ji++] = {edge_W2 + (size_t)l * HD * HD, 128, 128, oE2[l]};
        jobs.j[ji++] = {edge_W3 + (size_t)l * HD * HD, 128, 128, oE3[l]};
        jobs.j[ji++] = {node_W1 + (size_t)l * 2 * HD * HD, 256, 256, oN1[l]};
        jobs.j[ji++] = {node_W2 + (size_t)l * HD * HD, 128, 128, oN2[l]};
        jobs.j[ji++] = {node_W3 + (size_t)l * HD * HD, 128, 128, oN3[l]};
    }
    dim3 cg((128 * 384 + 255) / 256, NJOBS);
    conv_w_kernel<<<cg, 256>>>(jobs);

    const int edge_blocks = (NE + ROWS_CTA - 1) / ROWS_CTA;   // 1563
    const int node_blocks = (NN + ROWS_CTA - 1) / ROWS_CTA;   // 98
    const int nthr_blocks = (int)(((size_t)NN * HD + 255) / 256);

    // edge embedding: e = MLP(edge_attr)
    mma_mlp<0, 1, 1, 0><<<edge_blocks, 512, SMEM_DYN>>>(
        eattr, nullptr, oEmb1, oEmb2, oEmb3, 16,
        emb_b1, emb_b2, emb_b3, emb_g, emb_be, nullptr, eA, NE);

    const float* x_cur = x_in;
    float* e_cur = eA;
    for (int l = 0; l < 2; l++) {
        float* e_out = (l == 0) ? eB : out_e;
        float* x_out = (l == 0) ? xbuf : out_x;

        // agg must be zero before the fused scatter in the edge MLP
        zero_agg_kernel<<<nthr_blocks, 256>>>();

        // e_new = MLP([x[dst] | x[src] | e]) + e ; agg += e_new (fused scatter)
        mma_mlp<1, 6, 4, 1><<<edge_blocks, 512, SMEM_DYN>>>(
            x_cur, e_cur, oE1[l], oE2[l], oE3[l], 384,
            edge_b1 + l * HD, edge_b2 + l * HD, edge_b3 + l * HD,
            edge_g + l * HD, edge_be + l * HD, e_cur, e_out, NE);

        // x = MLP([x | agg]) + x
        mma_mlp<2, 4, 4, 0><<<node_blocks, 512, SMEM_DYN>>>(
            x_cur, agg, oN1[l], oN2[l], oN3[l], 256,
            node_b1 + l * HD, node_b2 + l * HD, node_b3 + l * HD,
            node_g + l * HD, node_be + l * HD, x_cur, x_out, NN);

        e_cur = e_out;
        x_cur = x_out;
    }
}

// round 16
// speedup vs baseline: 1.4979x; 1.1605x over previous
#include <cuda_runtime.h>
#include <cuda_fp16.h>
#include <cstdint>

#define NN 25000
#define NE 400000
#define HD 128
#define LN_EPS 1e-5f

// ================= device scratch =================
__device__ int   g_src[NE];
__device__ int   g_dst[NE];
__device__ int   g_is64;
__device__ float g_eA[(size_t)NE * HD];
__device__ float g_eB[(size_t)NE * HD];
__device__ float g_agg[(size_t)NN * HD];
__device__ float g_x[(size_t)NN * HD];
__device__ float g_Pa[(size_t)NN * HD];   // x . W1a  (dst part)
__device__ float g_Pb[(size_t)NN * HD];   // x . W1b  (src part)

// fp16 hi/lo weight pools, [n=128][Kpad] row-major per matrix (W = wh+wl exact)
#define POOL_ELEMS 335872
__device__ __align__(16) __half g_wh[POOL_ELEMS];
__device__ __align__(16) __half g_wl[POOL_ELEMS];

// ================= smem layout (dynamic, bytes) =================
#define LDT      144u
#define WB(i)    ((uint32_t)(i) * 36864u)
#define SL(i)    (73728u + (uint32_t)(i) * 36864u)
#define W_PAIR   18432u
#define SMEM_DYN 147456
#define ROWS_CTA 256
// f32 staging: floats at byte 0 (W+A consumed by then), stride 130

// ================= helpers =================
__device__ __forceinline__ uint32_t smem_u32(const void* p) {
    uint32_t a;
    asm("{ .reg .u64 t; cvta.to.shared.u64 t, %1; cvt.u32.u64 %0, t; }"
        : "=r"(a) : "l"(p));
    return a;
}
__device__ __forceinline__ void ldsm4(uint32_t addr, uint32_t* r) {
    asm volatile("ldmatrix.sync.aligned.m8n8.x4.shared.b16 {%0,%1,%2,%3}, [%4];"
                 : "=r"(r[0]), "=r"(r[1]), "=r"(r[2]), "=r"(r[3]) : "r"(addr));
}
__device__ __forceinline__ void mma16816(float* d, const uint32_t* a,
                                         uint32_t b0, uint32_t b1) {
    asm("mma.sync.aligned.m16n8k16.row.col.f32.f16.f16.f32 "
        "{%0,%1,%2,%3}, {%4,%5,%6,%7}, {%8,%9}, {%0,%1,%2,%3};"
        : "+f"(d[0]), "+f"(d[1]), "+f"(d[2]), "+f"(d[3])
        : "r"(a[0]), "r"(a[1]), "r"(a[2]), "r"(a[3]), "r"(b0), "r"(b1));
}
__device__ __forceinline__ void cp16(uint32_t dst, const void* src) {
    asm volatile("cp.async.cg.shared.global [%0], [%1], 16;"
                 :: "r"(dst), "l"(src));
}
#define CP_COMMIT() asm volatile("cp.async.commit_group;")
#define CP_WAIT0()  asm volatile("cp.async.wait_group 0;" ::: "memory")
__device__ __forceinline__ uint32_t pack2(float a, float b) {
    __half2 H = __floats2half2_rn(a, b);
    return *reinterpret_cast<uint32_t*>(&H);
}
__device__ __forceinline__ float silu(float v) {
    return __fdividef(v, 1.f + __expf(-v));
}

// ================= index prep =================
__global__ void detect_kernel(const int* __restrict__ raw) {
    __shared__ int cnt;
    if (threadIdx.x == 0) cnt = 0;
    __syncthreads();
    int c = 0;
    for (int t = threadIdx.x; t < 1024; t += blockDim.x)
        if (raw[2 * t + 1] != 0) c++;
    atomicAdd(&cnt, c);
    __syncthreads();
    if (threadIdx.x == 0) g_is64 = (cnt < 16) ? 1 : 0;
}
__global__ void convert_kernel(const int* __restrict__ raw) {
    int i = blockIdx.x * blockDim.x + threadIdx.x;
    if (i >= NE) return;
    int s, d;
    if (g_is64) {
        const long long* p = (const long long*)raw;
        s = (int)p[i];
        d = (int)p[NE + i];
    } else {
        s = raw[i];
        d = raw[NE + i];
    }
    if ((unsigned)s >= NN) s = 0;
    if ((unsigned)d >= NN) d = 0;
    g_src[i] = s;
    g_dst[i] = d;
}

// ================= weight split prep =================
#define NJOBS 15
struct WJob { const float* src; int Ksrc; int Kpad; int dst; };
struct WJobs { WJob j[NJOBS]; };
__global__ void conv_w_kernel(WJobs jobs) {
    WJob jb = jobs.j[blockIdx.y];
    int idx = blockIdx.x * 256 + threadIdx.x;
    if (idx >= 128 * jb.Kpad) return;
    int n = idx / jb.Kpad, k = idx % jb.Kpad;
    float v = (k < jb.Ksrc) ? jb.src[(size_t)k * 128 + n] : 0.f;
    __half h = __float2half_rn(v);
    float r = v - __half2float(h);
    g_wh[(size_t)jb.dst + (size_t)n * jb.Kpad + k] = h;
    g_wl[(size_t)jb.dst + (size_t)n * jb.Kpad + k] = __float2half_rn(r);
}

// ================= A gather (one 128-row half of the 256-row tile) =================
// MODE 0: emb (edge_attr, K=16); MODE 2: dense [in0|in1] 128+128;
// MODE 3: e-only (in1, chunk*64)
template <int MODE>
__device__ __forceinline__ void a_load(const float* __restrict__ in0,
                                       const float* __restrict__ in1,
                                       int chunk, int half, int row0, int rows,
                                       int t, float4* v) {
    const int r = (t >> 2) + half * 128;
    const int kh = (t & 3) << 4;          // 0,16,32,48
    const int gk = chunk * 64 + kh;
    const int row = row0 + r;
    const float* src = nullptr;
    if (MODE == 0) {
        if (kh == 0 && row < rows) src = in0 + (size_t)row * 16;
    } else if (MODE == 2) {
        if (row < rows) {
            int sect = gk >> 7;
            int coff = gk & 127;
            src = (sect ? in1 : in0) + (size_t)row * HD + coff;
        }
    } else {  // MODE 3
        if (row < rows) src = in1 + (size_t)row * HD + chunk * 64 + kh;
    }
    v[0] = v[1] = v[2] = v[3] = make_float4(0.f, 0.f, 0.f, 0.f);
    if (src) {
        v[0] = *(const float4*)(src);
        v[1] = *(const float4*)(src + 4);
        v[2] = *(const float4*)(src + 8);
        v[3] = *(const float4*)(src + 12);
    }
}

__device__ __forceinline__ void a_store(char* sm, uint32_t slot, int half,
                                        int t, const float4* v) {
    const int r = (t >> 2) + half * 128;
    const int kh = (t & 3) << 4;
    const uint32_t rbase = (uint32_t)r * LDT;
#pragma unroll
    for (int g = 0; g < 2; g++) {
        uint4 h;
        h.x = pack2(v[2 * g].x,     v[2 * g].y);
        h.y = pack2(v[2 * g].z,     v[2 * g].w);
        h.z = pack2(v[2 * g + 1].x, v[2 * g + 1].y);
        h.w = pack2(v[2 * g + 1].z, v[2 * g + 1].w);
        uint32_t off = rbase + (uint32_t)(kh + g * 8) * 2u;
        *(uint4*)(sm + slot + off) = h;
    }
}

// W tile (128 n x 64 k, hi+lo) via cp.async
__device__ __forceinline__ void load_w_async(uint32_t sb, uint32_t wb,
                                             int wofs, int kc, int Kpad, int t) {
    const int n = t >> 2;
    const int kh = (t & 3) << 4;
    if (kh >= Kpad) return;
    const __half* ph = g_wh + wofs + (size_t)n * Kpad + kc + kh;
    const __half* pl = g_wl + wofs + (size_t)n * Kpad + kc + kh;
    const uint32_t nb = (uint32_t)n * LDT;
#pragma unroll
    for (int g = 0; g < 2; g++) {
        uint32_t off = nb + (uint32_t)(kh + g * 8) * 2u;
        cp16(sb + wb + off, ph + g * 8);
        cp16(sb + wb + W_PAIR + off, pl + g * 8);
    }
}

// ================= warp MMA: 32(M) x 64(N), 2 passes (Ah x Wh + Ah x Wl) ==========
template <int K16S>
__device__ __forceinline__ void mma_chunk(uint32_t sb, uint32_t aB, uint32_t wB,
                                          float (&acc)[2][8][4], int m0, int n0, int lane) {
    const uint32_t wLo = wB + W_PAIR;
    const int rowA = m0 + (lane & 15);
    const int kselA = (lane >> 4) << 3;
    const uint32_t aB0 = (uint32_t)rowA * LDT;
    const uint32_t aB1 = aB0 + 16u * LDT;
    const int rowB = n0 + (lane & 7) + (((lane >> 4) & 1) << 3);
    const int kselB = ((lane >> 3) & 1) << 3;
#pragma unroll
    for (int ks = 0; ks < K16S; ks++) {
        const int k16 = ks * 16;
        uint32_t ah[2][4];
        uint32_t ak = (uint32_t)(k16 + kselA) * 2u;
        ldsm4(sb + aB + aB0 + ak, ah[0]);
        ldsm4(sb + aB + aB1 + ak, ah[1]);
        uint32_t bk = (uint32_t)(k16 + kselB) * 2u;
#pragma unroll
        for (int nb = 0; nb < 4; nb++) {
            uint32_t bh[4], bl[4];
            uint32_t bb = (uint32_t)(rowB + nb * 16) * LDT;
            ldsm4(sb + wB + bb + bk, bh);
            ldsm4(sb + wLo + bb + bk, bl);
#pragma unroll
            for (int mi = 0; mi < 2; mi++) {
                mma16816(acc[mi][nb * 2],     ah[mi], bh[0], bh[1]);
                mma16816(acc[mi][nb * 2 + 1], ah[mi], bh[2], bh[3]);
            }
#pragma unroll
            for (int mi = 0; mi < 2; mi++) {
                mma16816(acc[mi][nb * 2],     ah[mi], bl[0], bl[1]);
                mma16816(acc[mi][nb * 2 + 1], ah[mi], bl[2], bl[3]);
            }
        }
    }
}

__device__ __forceinline__ void zero_acc(float (&acc)[2][8][4]) {
#pragma unroll
    for (int mi = 0; mi < 2; mi++)
#pragma unroll
        for (int j = 0; j < 8; j++)
#pragma unroll
            for (int e = 0; e < 4; e++) acc[mi][j][e] = 0.f;
}

// ================= epilogues =================
__device__ __forceinline__ void epi_silu(char* sm, float (&acc)[2][8][4],
                                         const float* __restrict__ bias,
                                         int m0, int n0, int lane) {
    const int cq = (lane & 3) << 1;
    const int r0l = lane >> 2;
#pragma unroll
    for (int mi = 0; mi < 2; mi++)
#pragma unroll
        for (int j = 0; j < 8; j++) {
            int c = n0 + j * 8 + cq;
            float b0 = bias[c], b1 = bias[c + 1];
            uint32_t hiT = SL(c >> 6);
            int hc = c & 63;
#pragma unroll
            for (int h = 0; h < 2; h++) {
                float v0 = silu(acc[mi][j][2 * h] + b0);
                float v1 = silu(acc[mi][j][2 * h + 1] + b1);
                int r = m0 + mi * 16 + r0l + 8 * h;
                uint32_t off = (uint32_t)r * LDT + (uint32_t)(hc * 2);
                *(uint32_t*)(sm + hiT + off) = pack2(v0, v1);
            }
        }
}

// SiLU epilogue + gather-add of Pa[dst[row]] + Pb[src[row]] (edge layer 1)
__device__ __forceinline__ void epi_silu_g(char* sm, float (&acc)[2][8][4],
                                           const float* __restrict__ bias,
                                           const float* __restrict__ pa,
                                           const float* __restrict__ pb,
                                           int m0, int n0, int lane,
                                           int row0, int rows) {
    const int cq = (lane & 3) << 1;
    const int r0l = lane >> 2;
    const float* PA[2][2];
    const float* PB[2][2];
#pragma unroll
    for (int mi = 0; mi < 2; mi++)
#pragma unroll
        for (int h = 0; h < 2; h++) {
            int row = row0 + m0 + mi * 16 + r0l + 8 * h;
            if (row >= rows) row = 0;
            PA[mi][h] = pa + (size_t)g_dst[row] * HD;
            PB[mi][h] = pb + (size_t)g_src[row] * HD;
        }
#pragma unroll
    for (int mi = 0; mi < 2; mi++)
#pragma unroll
        for (int j = 0; j < 8; j++) {
            int c = n0 + j * 8 + cq;
            float b0 = bias[c], b1 = bias[c + 1];
            uint32_t hiT = SL(c >> 6);
            int hc = c & 63;
#pragma unroll
            for (int h = 0; h < 2; h++) {
                float2 qa = *(const float2*)(PA[mi][h] + c);
                float2 qb = *(const float2*)(PB[mi][h] + c);
                float v0 = silu(acc[mi][j][2 * h] + qa.x + qb.x + b0);
                float v1 = silu(acc[mi][j][2 * h + 1] + qa.y + qb.y + b1);
                int r = m0 + mi * 16 + r0l + 8 * h;
                uint32_t off = (uint32_t)r * LDT + (uint32_t)(hc * 2);
                *(uint32_t*)(sm + hiT + off) = pack2(v0, v1);
            }
        }
}

__device__ __forceinline__ void epi_ln(char* sm, float (&acc)[2][8][4],
                                       const float* __restrict__ bias,
                                       const float* __restrict__ gam,
                                       const float* __restrict__ bet,
                                       float (*sRed)[ROWS_CTA][2],
                                       int m0, int n0, int wn, int lane) {
    const int cq = (lane & 3) << 1;
    const int r0l = lane >> 2;
    float s[2][2] = {{0.f, 0.f}, {0.f, 0.f}};
    float q[2][2] = {{0.f, 0.f}, {0.f, 0.f}};
#pragma unroll
    for (int mi = 0; mi < 2; mi++)
#pragma unroll
        for (int j = 0; j < 8; j++) {
            int c = n0 + j * 8 + cq;
            float b0 = bias[c], b1 = bias[c + 1];
#pragma unroll
            for (int h = 0; h < 2; h++) {
                float v0 = acc[mi][j][2 * h] + b0;
                float v1 = acc[mi][j][2 * h + 1] + b1;
                s[mi][h] += v0 + v1;
                q[mi][h] += v0 * v0 + v1 * v1;
            }
        }
#pragma unroll
    for (int o = 1; o <= 2; o <<= 1)
#pragma unroll
        for (int mi = 0; mi < 2; mi++)
#pragma unroll
            for (int h = 0; h < 2; h++) {
                s[mi][h] += __shfl_xor_sync(0xffffffffu, s[mi][h], o);
                q[mi][h] += __shfl_xor_sync(0xffffffffu, q[mi][h], o);
            }
    if ((lane & 3) == 0) {
#pragma unroll
        for (int mi = 0; mi < 2; mi++)
#pragma unroll
            for (int h = 0; h < 2; h++) {
                int r = m0 + mi * 16 + r0l + 8 * h;
                sRed[wn][r][0] = s[mi][h];
                sRed[wn][r][1] = q[mi][h];
            }
    }
    __syncthreads();
    float mu[2][2], rs[2][2];
#pragma unroll
    for (int mi = 0; mi < 2; mi++)
#pragma unroll
        for (int h = 0; h < 2; h++) {
            int r = m0 + mi * 16 + r0l + 8 * h;
            float S = sRed[0][r][0] + sRed[1][r][0];
            float Q = sRed[0][r][1] + sRed[1][r][1];
            float m = S * (1.f / HD);
            float var = Q * (1.f / HD) - m * m;
            mu[mi][h] = m;
            rs[mi][h] = rsqrtf(var + LN_EPS);
        }
    float* so = (float*)sm;
#pragma unroll
    for (int mi = 0; mi < 2; mi++)
#pragma unroll
        for (int j = 0; j < 8; j++) {
            int c = n0 + j * 8 + cq;
            float b0 = bias[c], b1 = bias[c + 1];
            float g0 = gam[c], g1 = gam[c + 1];
            float e0 = bet[c], e1 = bet[c + 1];
#pragma unroll
            for (int h = 0; h < 2; h++) {
                int r = m0 + mi * 16 + r0l + 8 * h;
                float v0 = acc[mi][j][2 * h] + b0;
                float v1 = acc[mi][j][2 * h + 1] + b1;
                so[r * 130 + c]     = (v0 - mu[mi][h]) * rs[mi][h] * g0 + e0;
                so[r * 130 + c + 1] = (v1 - mu[mi][h]) * rs[mi][h] * g1 + e1;
            }
        }
}

// ================= fused MLP kernel =================
// MODE 0: emb; MODE 2: node [x|agg]; MODE 3: edge (e-only layer1 + P gather epi)
// SCAT: fused segment-sum; EPIG: gather-add P in layer-1 epilogue
template <int MODE, int NCH, int K16S1, int SCAT, int EPIG>
__global__ __launch_bounds__(512, 1) void mma_mlp(
    const float* __restrict__ in0, const float* __restrict__ in1,
    const float* __restrict__ pa, const float* __restrict__ pb,
    int o1, int kc1, int o2, int o3, int Kpad1,
    const float* __restrict__ b1, const float* __restrict__ b2,
    const float* __restrict__ b3, const float* __restrict__ gam,
    const float* __restrict__ bet,
    const float* __restrict__ resid, float* __restrict__ out, int rows) {
    extern __shared__ char sm[];
    __shared__ float sRed[2][ROWS_CTA][2];
    const int t = threadIdx.x;
    const uint32_t sb = smem_u32(sm);
    const int lane = t & 31, w = t >> 5;
    const int m0 = (w & 7) * 32, n0 = (w >> 3) * 64, wn = w >> 3;
    const int row0 = blockIdx.x * ROWS_CTA;
    float acc[2][8][4];
    float4 v[4];

    // ---- layer 1: pipelined 64-col chunks ----
    zero_acc(acc);
    for (int c = 0; c < NCH; c++) {
        __syncthreads();
        a_load<MODE>(in0, in1, c, 0, row0, rows, t, v);
        a_store((char*)sm, SL(c & 1), 0, t, v);
        a_load<MODE>(in0, in1, c, 1, row0, rows, t, v);
        a_store((char*)sm, SL(c & 1), 1, t, v);
        load_w_async(sb, WB(c & 1), o1, kc1 + c * 64, Kpad1, t);
        CP_COMMIT();
        if (c > 0) mma_chunk<K16S1>(sb, SL((c - 1) & 1), WB((c - 1) & 1), acc, m0, n0, lane);
        CP_WAIT0();
    }
    __syncthreads();
    mma_chunk<K16S1>(sb, SL((NCH - 1) & 1), WB((NCH - 1) & 1), acc, m0, n0, lane);
    __syncthreads();

    // ---- layer 2 ----
    load_w_async(sb, WB(0), o2, 0, 128, t);
    load_w_async(sb, WB(1), o2, 64, 128, t);
    CP_COMMIT();
    if (EPIG)
        epi_silu_g((char*)sm, acc, b1, pa, pb, m0, n0, lane, row0, rows);
    else
        epi_silu((char*)sm, acc, b1, m0, n0, lane);
    zero_acc(acc);
    CP_WAIT0();
    __syncthreads();
    mma_chunk<4>(sb, SL(0), WB(0), acc, m0, n0, lane);
    mma_chunk<4>(sb, SL(1), WB(1), acc, m0, n0, lane);
    __syncthreads();

    // ---- layer 3 ----
    load_w_async(sb, WB(0), o3, 0, 128, t);
    load_w_async(sb, WB(1), o3, 64, 128, t);
    CP_COMMIT();
    epi_silu((char*)sm, acc, b2, m0, n0, lane);
    zero_acc(acc);
    CP_WAIT0();
    __syncthreads();
    mma_chunk<4>(sb, SL(0), WB(0), acc, m0, n0, lane);
    mma_chunk<4>(sb, SL(1), WB(1), acc, m0, n0, lane);
    __syncthreads();
    epi_ln((char*)sm, acc, b3, gam, bet, sRed, m0, n0, wn, lane);
    __syncthreads();

    // ---- residual + vectorized store (+ fused segment-sum scatter) ----
    const float* so = (const float*)sm;
    const int c4 = lane << 2;
    for (int r = w; r < ROWS_CTA; r += 16) {
        int row = row0 + r;
        if (row < rows) {
            const float* sr = so + r * 130 + c4;
            float4 y = make_float4(sr[0], sr[1], sr[2], sr[3]);
            if (MODE != 0) {
                float4 rv = *(const float4*)(resid + (size_t)row * HD + c4);
                y.x += rv.x; y.y += rv.y; y.z += rv.z; y.w += rv.w;
            }
            *(float4*)(out + (size_t)row * HD + c4) = y;
            if (SCAT) {
                float* p = g_agg + (size_t)g_dst[row] * HD + c4;
                asm volatile("red.global.add.v4.f32 [%0], {%1, %2, %3, %4};"
                             :: "l"(p), "f"(y.x), "f"(y.y), "f"(y.z), "f"(y.w)
                             : "memory");
            }
        }
    }
}

// ================= P precompute: out = x . W1[kc0:kc0+128] (single GEMM) =========
__global__ __launch_bounds__(512, 1) void p_gemm(
    const float* __restrict__ x, int wofs, int kc0,
    float* __restrict__ outP, int rows) {
    extern __shared__ char sm[];
    const int t = threadIdx.x;
    const uint32_t sb = smem_u32(sm);
    const int lane = t & 31, w = t >> 5;
    const int m0 = (w & 7) * 32, n0 = (w >> 3) * 64;
    const int row0 = blockIdx.x * ROWS_CTA;
    float acc[2][8][4];
    float4 v[4];
    zero_acc(acc);
    a_load<2>(x, x, 0, 0, row0, rows, t, v);
    a_store((char*)sm, SL(0), 0, t, v);
    a_load<2>(x, x, 0, 1, row0, rows, t, v);
    a_store((char*)sm, SL(0), 1, t, v);
    a_load<2>(x, x, 1, 0, row0, rows, t, v);
    a_store((char*)sm, SL(1), 0, t, v);
    a_load<2>(x, x, 1, 1, row0, rows, t, v);
    a_store((char*)sm, SL(1), 1, t, v);
    load_w_async(sb, WB(0), wofs, kc0, 384, t);
    load_w_async(sb, WB(1), wofs, kc0 + 64, 384, t);
    CP_COMMIT();
    CP_WAIT0();
    __syncthreads();
    mma_chunk<4>(sb, SL(0), WB(0), acc, m0, n0, lane);
    mma_chunk<4>(sb, SL(1), WB(1), acc, m0, n0, lane);
    __syncthreads();
    // stage f32 + coalesced store
    const int cq = (lane & 3) << 1;
    const int r0l = lane >> 2;
    float* so = (float*)sm;
#pragma unroll
    for (int mi = 0; mi < 2; mi++)
#pragma unroll
        for (int j = 0; j < 8; j++) {
            int c = n0 + j * 8 + cq;
#pragma unroll
            for (int h = 0; h < 2; h++) {
                int r = m0 + mi * 16 + r0l + 8 * h;
                so[r * 130 + c]     = acc[mi][j][2 * h];
                so[r * 130 + c + 1] = acc[mi][j][2 * h + 1];
            }
        }
    __syncthreads();
    const int c4 = lane << 2;
    for (int r = w; r < ROWS_CTA; r += 16) {
        int row = row0 + r;
        if (row < rows) {
            const float* sr = so + r * 130 + c4;
            float4 y = make_float4(sr[0], sr[1], sr[2], sr[3]);
            *(float4*)(outP + (size_t)row * HD + c4) = y;
        }
    }
}

// ================= aggregation buffer zero =================
__global__ void zero_agg_kernel() {
    size_t i = (size_t)blockIdx.x * blockDim.x + threadIdx.x;
    if (i < (size_t)NN * HD) g_agg[i] = 0.f;
}

// ================= launch =================
extern "C" void kernel_launch(void* const* d_in, const int* in_sizes, int n_in,
                              void* d_out, int out_size) {
    const float* x_in    = (const float*)d_in[0];
    const int*   eidx    = (const int*)d_in[1];
    const float* eattr   = (const float*)d_in[2];
    const float* emb_W1  = (const float*)d_in[3];
    const float* emb_b1  = (const float*)d_in[4];
    const float* emb_W2  = (const float*)d_in[5];
    const float* emb_b2  = (const float*)d_in[6];
    const float* emb_W3  = (const float*)d_in[7];
    const float* emb_b3  = (const float*)d_in[8];
    const float* emb_g   = (const float*)d_in[9];
    const float* emb_be  = (const float*)d_in[10];
    const float* edge_W1 = (const float*)d_in[11];
    const float* edge_b1 = (const float*)d_in[12];
    const float* edge_W2 = (const float*)d_in[13];
    const float* edge_b2 = (const float*)d_in[14];
    const float* edge_W3 = (const float*)d_in[15];
    const float* edge_b3 = (const float*)d_in[16];
    const float* edge_g  = (const float*)d_in[17];
    const float* edge_be = (const float*)d_in[18];
    const float* node_W1 = (const float*)d_in[19];
    const float* node_b1 = (const float*)d_in[20];
    const float* node_W2 = (const float*)d_in[21];
    const float* node_b2 = (const float*)d_in[22];
    const float* node_W3 = (const float*)d_in[23];
    const float* node_b3 = (const float*)d_in[24];
    const float* node_g  = (const float*)d_in[25];
    const float* node_be = (const float*)d_in[26];

    float* out_x = (float*)d_out;
    float* out_e = (float*)d_out + (size_t)NN * HD;

    float *eA, *eB, *agg, *xbuf, *Pa, *Pb;
    cudaGetSymbolAddress((void**)&eA, g_eA);
    cudaGetSymbolAddress((void**)&eB, g_eB);
    cudaGetSymbolAddress((void**)&agg, g_agg);
    cudaGetSymbolAddress((void**)&xbuf, g_x);
    cudaGetSymbolAddress((void**)&Pa, g_Pa);
    cudaGetSymbolAddress((void**)&Pb, g_Pb);

    cudaFuncSetAttribute((const void*)mma_mlp<0, 1, 1, 0, 0>, cudaFuncAttributeMaxDynamicSharedMemorySize, SMEM_DYN);
    cudaFuncSetAttribute((const void*)mma_mlp<3, 2, 4, 1, 1>, cudaFuncAttributeMaxDynamicSharedMemorySize, SMEM_DYN);
    cudaFuncSetAttribute((const void*)mma_mlp<2, 4, 4, 0, 0>, cudaFuncAttributeMaxDynamicSharedMemorySize, SMEM_DYN);
    cudaFuncSetAttribute((const void*)p_gemm, cudaFuncAttributeMaxDynamicSharedMemorySize, SMEM_DYN);

    // index prep (clamped)
    detect_kernel<<<1, 256>>>(eidx);
    convert_kernel<<<(NE + 255) / 256, 256>>>(eidx);

    // pool offsets (elements)
    const int oEmb1 = 0, oEmb2 = 8192, oEmb3 = 24576;
    int oE1[2], oE2[2], oE3[2], oN1[2], oN2[2], oN3[2];
    int base = 40960;
    for (int l = 0; l < 2; l++) {
        oE1[l] = base;
        oE2[l] = base + 49152;
        oE3[l] = base + 65536;
        oN1[l] = base + 81920;
        oN2[l] = base + 114688;
        oN3[l] = base + 131072;
        base += 147456;
    }

    WJobs jobs;
    int ji = 0;
    jobs.j[ji++] = {emb_W1, 16, 16, oEmb1};
    jobs.j[ji++] = {emb_W2, 128, 128, oEmb2};
    jobs.j[ji++] = {emb_W3, 128, 128, oEmb3};
    for (int l = 0; l < 2; l++) {
        jobs.j[ji++] = {edge_W1 + (size_t)l * 3 * HD * HD, 384, 384, oE1[l]};
        jobs.j[ji++] = {edge_W2 + (size_t)l * HD * HD, 128, 128, oE2[l]};
        jobs.j[ji++] = {edge_W3 + (size_t)l * HD * HD, 128, 128, oE3[l]};
        jobs.j[ji++] = {node_W1 + (size_t)l * 2 * HD * HD, 256, 256, oN1[l]};
        jobs.j[ji++] = {node_W2 + (size_t)l * HD * HD, 128, 128, oN2[l]};
        jobs.j[ji++] = {node_W3 + (size_t)l * HD * HD, 128, 128, oN3[l]};
    }
    dim3 cg((128 * 384 + 255) / 256, NJOBS);
    conv_w_kernel<<<cg, 256>>>(jobs);

    const int edge_blocks = (NE + ROWS_CTA - 1) / ROWS_CTA;   // 1563
    const int node_blocks = (NN + ROWS_CTA - 1) / ROWS_CTA;   // 98
    const int nthr_blocks = (int)(((size_t)NN * HD + 255) / 256);

    // edge embedding: e = MLP(edge_attr)
    mma_mlp<0, 1, 1, 0, 0><<<edge_blocks, 512, SMEM_DYN>>>(
        eattr, nullptr, nullptr, nullptr, oEmb1, 0, oEmb2, oEmb3, 16,
        emb_b1, emb_b2, emb_b3, emb_g, emb_be, nullptr, eA, NE);

    const float* x_cur = x_in;
    float* e_cur = eA;
    for (int l = 0; l < 2; l++) {
        float* e_out = (l == 0) ? eB : out_e;
        float* x_out = (l == 0) ? xbuf : out_x;

        // Pa = x . W1[:,0:128] (dst), Pb = x . W1[:,128:256] (src)
        p_gemm<<<node_blocks, 512, SMEM_DYN>>>(x_cur, oE1[l], 0, Pa, NN);
        p_gemm<<<node_blocks, 512, SMEM_DYN>>>(x_cur, oE1[l], 128, Pb, NN);

        // agg must be zero before the fused scatter in the edge MLP
        zero_agg_kernel<<<nthr_blocks, 256>>>();

        // e_new = MLP([x_dst|x_src|e]) + e via e.W1c MMA + P gather; agg += e_new
        mma_mlp<3, 2, 4, 1, 1><<<edge_blocks, 512, SMEM_DYN>>>(
            nullptr, e_cur, Pa, Pb, oE1[l], 256, oE2[l], oE3[l], 384,
            edge_b1 + l * HD, edge_b2 + l * HD, edge_b3 + l * HD,
            edge_g + l * HD, edge_be + l * HD, e_cur, e_out, NE);

        // x = MLP([x | agg]) + x
        mma_mlp<2, 4, 4, 0, 0><<<node_blocks, 512, SMEM_DYN>>>(
            x_cur, agg, nullptr, nullptr, oN1[l], 0, oN2[l], oN3[l], 256,
            node_b1 + l * HD, node_b2 + l * HD, node_b3 + l * HD,
            node_g + l * HD, node_be + l * HD, x_cur, x_out, NN);

        e_cur = e_out;
        x_cur = x_out;
    }
}

// round 17
// speedup vs baseline: 1.5260x; 1.0187x over previous
#include <cuda_runtime.h>
#include <cuda_fp16.h>
#include <cstdint>

#define NN 25000
#define NE 400000
#define HD 128
#define LN_EPS 1e-5f

// ================= device scratch =================
__device__ int   g_src[NE];
__device__ int   g_dst[NE];
__device__ int   g_is64;
__device__ float g_eB[(size_t)NE * HD];
__device__ float g_agg[(size_t)NN * HD];
__device__ float g_x[(size_t)NN * HD];
__device__ float g_Pa[(size_t)NN * HD];
__device__ float g_Pb[(size_t)NN * HD];

// fp16 hi/lo weight pools, [n=128][Kpad] row-major per matrix (W = wh+wl exact)
#define POOL_ELEMS 335872
__device__ __align__(16) __half g_wh[POOL_ELEMS];
__device__ __align__(16) __half g_wl[POOL_ELEMS];

// ================= smem layout (dynamic, bytes) =================
#define LDT      144u
#define WB(i)    ((uint32_t)(i) * 36864u)
#define SL(i)    (73728u + (uint32_t)(i) * 36864u)
#define W_PAIR   18432u
#define E16      147456u                 // fp16 e residual, 256 rows x 256 B
#define SMEM_DYN   147456
#define SMEM_FUSED 212992
#define ROWS_CTA 256
// f32 staging: floats at byte 0 (W+A consumed by then), stride 130

// ================= helpers =================
__device__ __forceinline__ uint32_t smem_u32(const void* p) {
    uint32_t a;
    asm("{ .reg .u64 t; cvta.to.shared.u64 t, %1; cvt.u32.u64 %0, t; }"
        : "=r"(a) : "l"(p));
    return a;
}
__device__ __forceinline__ void ldsm4(uint32_t addr, uint32_t* r) {
    asm volatile("ldmatrix.sync.aligned.m8n8.x4.shared.b16 {%0,%1,%2,%3}, [%4];"
                 : "=r"(r[0]), "=r"(r[1]), "=r"(r[2]), "=r"(r[3]) : "r"(addr));
}
__device__ __forceinline__ void mma16816(float* d, const uint32_t* a,
                                         uint32_t b0, uint32_t b1) {
    asm("mma.sync.aligned.m16n8k16.row.col.f32.f16.f16.f32 "
        "{%0,%1,%2,%3}, {%4,%5,%6,%7}, {%8,%9}, {%0,%1,%2,%3};"
        : "+f"(d[0]), "+f"(d[1]), "+f"(d[2]), "+f"(d[3])
        : "r"(a[0]), "r"(a[1]), "r"(a[2]), "r"(a[3]), "r"(b0), "r"(b1));
}
__device__ __forceinline__ void cp16(uint32_t dst, const void* src) {
    asm volatile("cp.async.cg.shared.global [%0], [%1], 16;"
                 :: "r"(dst), "l"(src));
}
#define CP_COMMIT() asm volatile("cp.async.commit_group;")
#define CP_WAIT0()  asm volatile("cp.async.wait_group 0;" ::: "memory")
__device__ __forceinline__ uint32_t pack2(float a, float b) {
    __half2 H = __floats2half2_rn(a, b);
    return *reinterpret_cast<uint32_t*>(&H);
}
__device__ __forceinline__ float silu(float v) {
    return __fdividef(v, 1.f + __expf(-v));
}

// ================= index prep =================
__global__ void detect_kernel(const int* __restrict__ raw) {
    __shared__ int cnt;
    if (threadIdx.x == 0) cnt = 0;
    __syncthreads();
    int c = 0;
    for (int t = threadIdx.x; t < 1024; t += blockDim.x)
        if (raw[2 * t + 1] != 0) c++;
    atomicAdd(&cnt, c);
    __syncthreads();
    if (threadIdx.x == 0) g_is64 = (cnt < 16) ? 1 : 0;
}
__global__ void convert_kernel(const int* __restrict__ raw) {
    int i = blockIdx.x * blockDim.x + threadIdx.x;
    if (i >= NE) return;
    int s, d;
    if (g_is64) {
        const long long* p = (const long long*)raw;
        s = (int)p[i];
        d = (int)p[NE + i];
    } else {
        s = raw[i];
        d = raw[NE + i];
    }
    if ((unsigned)s >= NN) s = 0;
    if ((unsigned)d >= NN) d = 0;
    g_src[i] = s;
    g_dst[i] = d;
}

// ================= weight split prep =================
#define NJOBS 15
struct WJob { const float* src; int Ksrc; int Kpad; int dst; };
struct WJobs { WJob j[NJOBS]; };
__global__ void conv_w_kernel(WJobs jobs) {
    WJob jb = jobs.j[blockIdx.y];
    int idx = blockIdx.x * 256 + threadIdx.x;
    if (idx >= 128 * jb.Kpad) return;
    int n = idx / jb.Kpad, k = idx % jb.Kpad;
    float v = (k < jb.Ksrc) ? jb.src[(size_t)k * 128 + n] : 0.f;
    __half h = __float2half_rn(v);
    float r = v - __half2float(h);
    g_wh[(size_t)jb.dst + (size_t)n * jb.Kpad + k] = h;
    g_wl[(size_t)jb.dst + (size_t)n * jb.Kpad + k] = __float2half_rn(r);
}

// ================= A gather =================
// MODE 0: emb edge_attr (K=16); MODE 2: dense [in0|in1]; MODE 3: e-only (in1)
template <int MODE>
__device__ __forceinline__ void a_load(const float* __restrict__ in0,
                                       const float* __restrict__ in1,
                                       int chunk, int half, int row0, int rows,
                                       int t, float4* v) {
    const int r = (t >> 2) + half * 128;
    const int kh = (t & 3) << 4;
    const int gk = chunk * 64 + kh;
    const int row = row0 + r;
    const float* src = nullptr;
    if (MODE == 0) {
        if (kh == 0 && row < rows) src = in0 + (size_t)row * 16;
    } else if (MODE == 2) {
        if (row < rows) {
            int sect = gk >> 7;
            int coff = gk & 127;
            src = (sect ? in1 : in0) + (size_t)row * HD + coff;
        }
    } else {
        if (row < rows) src = in1 + (size_t)row * HD + chunk * 64 + kh;
    }
    v[0] = v[1] = v[2] = v[3] = make_float4(0.f, 0.f, 0.f, 0.f);
    if (src) {
        v[0] = *(const float4*)(src);
        v[1] = *(const float4*)(src + 4);
        v[2] = *(const float4*)(src + 8);
        v[3] = *(const float4*)(src + 12);
    }
}

__device__ __forceinline__ void a_store(char* sm, uint32_t slot, int half,
                                        int t, const float4* v) {
    const int r = (t >> 2) + half * 128;
    const int kh = (t & 3) << 4;
    const uint32_t rbase = (uint32_t)r * LDT;
#pragma unroll
    for (int g = 0; g < 2; g++) {
        uint4 h;
        h.x = pack2(v[2 * g].x,     v[2 * g].y);
        h.y = pack2(v[2 * g].z,     v[2 * g].w);
        h.z = pack2(v[2 * g + 1].x, v[2 * g + 1].y);
        h.w = pack2(v[2 * g + 1].z, v[2 * g + 1].w);
        uint32_t off = rbase + (uint32_t)(kh + g * 8) * 2u;
        *(uint4*)(sm + slot + off) = h;
    }
}

__device__ __forceinline__ void load_w_async(uint32_t sb, uint32_t wb,
                                             int wofs, int kc, int Kpad, int t) {
    const int n = t >> 2;
    const int kh = (t & 3) << 4;
    if (kh >= Kpad) return;
    const __half* ph = g_wh + wofs + (size_t)n * Kpad + kc + kh;
    const __half* pl = g_wl + wofs + (size_t)n * Kpad + kc + kh;
    const uint32_t nb = (uint32_t)n * LDT;
#pragma unroll
    for (int g = 0; g < 2; g++) {
        uint32_t off = nb + (uint32_t)(kh + g * 8) * 2u;
        cp16(sb + wb + off, ph + g * 8);
        cp16(sb + wb + W_PAIR + off, pl + g * 8);
    }
}

// ================= warp MMA: 32x64, 2 passes =================
template <int K16S>
__device__ __forceinline__ void mma_chunk(uint32_t sb, uint32_t aB, uint32_t wB,
                                          float (&acc)[2][8][4], int m0, int n0, int lane) {
    const uint32_t wLo = wB + W_PAIR;
    const int rowA = m0 + (lane & 15);
    const int kselA = (lane >> 4) << 3;
    const uint32_t aB0 = (uint32_t)rowA * LDT;
    const uint32_t aB1 = aB0 + 16u * LDT;
    const int rowB = n0 + (lane & 7) + (((lane >> 4) & 1) << 3);
    const int kselB = ((lane >> 3) & 1) << 3;
#pragma unroll
    for (int ks = 0; ks < K16S; ks++) {
        const int k16 = ks * 16;
        uint32_t ah[2][4];
        uint32_t ak = (uint32_t)(k16 + kselA) * 2u;
        ldsm4(sb + aB + aB0 + ak, ah[0]);
        ldsm4(sb + aB + aB1 + ak, ah[1]);
        uint32_t bk = (uint32_t)(k16 + kselB) * 2u;
#pragma unroll
        for (int nb = 0; nb < 4; nb++) {
            uint32_t bh[4], bl[4];
            uint32_t bb = (uint32_t)(rowB + nb * 16) * LDT;
            ldsm4(sb + wB + bb + bk, bh);
            ldsm4(sb + wLo + bb + bk, bl);
#pragma unroll
            for (int mi = 0; mi < 2; mi++) {
                mma16816(acc[mi][nb * 2],     ah[mi], bh[0], bh[1]);
                mma16816(acc[mi][nb * 2 + 1], ah[mi], bh[2], bh[3]);
            }
#pragma unroll
            for (int mi = 0; mi < 2; mi++) {
                mma16816(acc[mi][nb * 2],     ah[mi], bl[0], bl[1]);
                mma16816(acc[mi][nb * 2 + 1], ah[mi], bl[2], bl[3]);
            }
        }
    }
}

__device__ __forceinline__ void zero_acc(float (&acc)[2][8][4]) {
#pragma unroll
    for (int mi = 0; mi < 2; mi++)
#pragma unroll
        for (int j = 0; j < 8; j++)
#pragma unroll
            for (int e = 0; e < 4; e++) acc[mi][j][e] = 0.f;
}

// ================= epilogues =================
__device__ __forceinline__ void epi_silu(char* sm, float (&acc)[2][8][4],
                                         const float* __restrict__ bias,
                                         int m0, int n0, int lane) {
    const int cq = (lane & 3) << 1;
    const int r0l = lane >> 2;
#pragma unroll
    for (int mi = 0; mi < 2; mi++)
#pragma unroll
        for (int j = 0; j < 8; j++) {
            int c = n0 + j * 8 + cq;
            float b0 = bias[c], b1 = bias[c + 1];
            uint32_t hiT = SL(c >> 6);
            int hc = c & 63;
#pragma unroll
            for (int h = 0; h < 2; h++) {
                float v0 = silu(acc[mi][j][2 * h] + b0);
                float v1 = silu(acc[mi][j][2 * h + 1] + b1);
                int r = m0 + mi * 16 + r0l + 8 * h;
                uint32_t off = (uint32_t)r * LDT + (uint32_t)(hc * 2);
                *(uint32_t*)(sm + hiT + off) = pack2(v0, v1);
            }
        }
}

__device__ __forceinline__ void epi_silu_g(char* sm, float (&acc)[2][8][4],
                                           const float* __restrict__ bias,
                                           const float* __restrict__ pa,
                                           const float* __restrict__ pb,
                                           int m0, int n0, int lane,
                                           int row0, int rows) {
    const int cq = (lane & 3) << 1;
    const int r0l = lane >> 2;
    const float* PA[2][2];
    const float* PB[2][2];
#pragma unroll
    for (int mi = 0; mi < 2; mi++)
#pragma unroll
        for (int h = 0; h < 2; h++) {
            int row = row0 + m0 + mi * 16 + r0l + 8 * h;
            if (row >= rows) row = 0;
            PA[mi][h] = pa + (size_t)g_dst[row] * HD;
            PB[mi][h] = pb + (size_t)g_src[row] * HD;
        }
#pragma unroll
    for (int mi = 0; mi < 2; mi++)
#pragma unroll
        for (int j = 0; j < 8; j++) {
            int c = n0 + j * 8 + cq;
            float b0 = bias[c], b1 = bias[c + 1];
            uint32_t hiT = SL(c >> 6);
            int hc = c & 63;
#pragma unroll
            for (int h = 0; h < 2; h++) {
                float2 qa = *(const float2*)(PA[mi][h] + c);
                float2 qb = *(const float2*)(PB[mi][h] + c);
                float v0 = silu(acc[mi][j][2 * h] + qa.x + qb.x + b0);
                float v1 = silu(acc[mi][j][2 * h + 1] + qa.y + qb.y + b1);
                int r = m0 + mi * 16 + r0l + 8 * h;
                uint32_t off = (uint32_t)r * LDT + (uint32_t)(hc * 2);
                *(uint32_t*)(sm + hiT + off) = pack2(v0, v1);
            }
        }
}

// LN stats helper: fills mu/rs per (mi,h)
__device__ __forceinline__ void ln_stats(float (&acc)[2][8][4],
                                         const float* __restrict__ bias,
                                         float (*sRed)[ROWS_CTA][2],
                                         int m0, int n0, int wn, int lane,
                                         float (&mu)[2][2], float (&rs)[2][2]) {
    const int cq = (lane & 3) << 1;
    const int r0l = lane >> 2;
    float s[2][2] = {{0.f, 0.f}, {0.f, 0.f}};
    float q[2][2] = {{0.f, 0.f}, {0.f, 0.f}};
#pragma unroll
    for (int mi = 0; mi < 2; mi++)
#pragma unroll
        for (int j = 0; j < 8; j++) {
            int c = n0 + j * 8 + cq;
            float b0 = bias[c], b1 = bias[c + 1];
#pragma unroll
            for (int h = 0; h < 2; h++) {
                float v0 = acc[mi][j][2 * h] + b0;
                float v1 = acc[mi][j][2 * h + 1] + b1;
                s[mi][h] += v0 + v1;
                q[mi][h] += v0 * v0 + v1 * v1;
            }
        }
#pragma unroll
    for (int o = 1; o <= 2; o <<= 1)
#pragma unroll
        for (int mi = 0; mi < 2; mi++)
#pragma unroll
            for (int h = 0; h < 2; h++) {
                s[mi][h] += __shfl_xor_sync(0xffffffffu, s[mi][h], o);
                q[mi][h] += __shfl_xor_sync(0xffffffffu, q[mi][h], o);
            }
    if ((lane & 3) == 0) {
#pragma unroll
        for (int mi = 0; mi < 2; mi++)
#pragma unroll
            for (int h = 0; h < 2; h++) {
                int r = m0 + mi * 16 + r0l + 8 * h;
                sRed[wn][r][0] = s[mi][h];
                sRed[wn][r][1] = q[mi][h];
            }
    }
    __syncthreads();
#pragma unroll
    for (int mi = 0; mi < 2; mi++)
#pragma unroll
        for (int h = 0; h < 2; h++) {
            int r = m0 + mi * 16 + r0l + 8 * h;
            float S = sRed[0][r][0] + sRed[1][r][0];
            float Q = sRed[0][r][1] + sRed[1][r][1];
            float m = S * (1.f / HD);
            float var = Q * (1.f / HD) - m * m;
            mu[mi][h] = m;
            rs[mi][h] = rsqrtf(var + LN_EPS);
        }
}

// LN -> f32 staging (stride 130 at byte 0)
__device__ __forceinline__ void epi_ln(char* sm, float (&acc)[2][8][4],
                                       const float* __restrict__ bias,
                                       const float* __restrict__ gam,
                                       const float* __restrict__ bet,
                                       float (*sRed)[ROWS_CTA][2],
                                       int m0, int n0, int wn, int lane) {
    float mu[2][2], rs[2][2];
    ln_stats(acc, bias, sRed, m0, n0, wn, lane, mu, rs);
    const int cq = (lane & 3) << 1;
    const int r0l = lane >> 2;
    float* so = (float*)sm;
#pragma unroll
    for (int mi = 0; mi < 2; mi++)
#pragma unroll
        for (int j = 0; j < 8; j++) {
            int c = n0 + j * 8 + cq;
            float b0 = bias[c], b1 = bias[c + 1];
            float g0 = gam[c], g1 = gam[c + 1];
            float e0 = bet[c], e1 = bet[c + 1];
#pragma unroll
            for (int h = 0; h < 2; h++) {
                int r = m0 + mi * 16 + r0l + 8 * h;
                float v0 = acc[mi][j][2 * h] + b0;
                float v1 = acc[mi][j][2 * h + 1] + b1;
                so[r * 130 + c]     = (v0 - mu[mi][h]) * rs[mi][h] * g0 + e0;
                so[r * 130 + c + 1] = (v1 - mu[mi][h]) * rs[mi][h] * g1 + e1;
            }
        }
}

// LN -> packed fp16 into SL tiles (for next MMA) + linear E16 (residual copy)
__device__ __forceinline__ void epi_ln_pack(char* sm, float (&acc)[2][8][4],
                                            const float* __restrict__ bias,
                                            const float* __restrict__ gam,
                                            const float* __restrict__ bet,
                                            float (*sRed)[ROWS_CTA][2],
                                            int m0, int n0, int wn, int lane) {
    float mu[2][2], rs[2][2];
    ln_stats(acc, bias, sRed, m0, n0, wn, lane, mu, rs);
    const int cq = (lane & 3) << 1;
    const int r0l = lane >> 2;
#pragma unroll
    for (int mi = 0; mi < 2; mi++)
#pragma unroll
        for (int j = 0; j < 8; j++) {
            int c = n0 + j * 8 + cq;
            float b0 = bias[c], b1 = bias[c + 1];
            float g0 = gam[c], g1 = gam[c + 1];
            float e0 = bet[c], e1 = bet[c + 1];
            uint32_t hiT = SL(c >> 6);
            int hc = c & 63;
#pragma unroll
            for (int h = 0; h < 2; h++) {
                int r = m0 + mi * 16 + r0l + 8 * h;
                float v0 = (acc[mi][j][2 * h] + b0 - mu[mi][h]) * rs[mi][h] * g0 + e0;
                float v1 = (acc[mi][j][2 * h + 1] + b1 - mu[mi][h]) * rs[mi][h] * g1 + e1;
                uint32_t p = pack2(v0, v1);
                *(uint32_t*)(sm + hiT + (uint32_t)r * LDT + (uint32_t)(hc * 2)) = p;
                *(uint32_t*)(sm + E16 + (uint32_t)r * 256u + (uint32_t)(c * 2)) = p;
            }
        }
}

// ================= standard fused MLP kernel =================
// MODE 2: node [x|agg]; MODE 3: edge (e-only layer1 + P gather epi)
template <int MODE, int NCH, int K16S1, int SCAT, int EPIG>
__global__ __launch_bounds__(512, 1) void mma_mlp(
    const float* __restrict__ in0, const float* __restrict__ in1,
    const float* __restrict__ pa, const float* __restrict__ pb,
    int o1, int kc1, int o2, int o3, int Kpad1,
    const float* __restrict__ b1, const float* __restrict__ b2,
    const float* __restrict__ b3, const float* __restrict__ gam,
    const float* __restrict__ bet,
    const float* __restrict__ resid, float* __restrict__ out, int rows) {
    extern __shared__ char sm[];
    __shared__ float sRed[2][ROWS_CTA][2];
    const int t = threadIdx.x;
    const uint32_t sb = smem_u32(sm);
    const int lane = t & 31, w = t >> 5;
    const int m0 = (w & 7) * 32, n0 = (w >> 3) * 64, wn = w >> 3;
    const int row0 = blockIdx.x * ROWS_CTA;
    float acc[2][8][4];
    float4 v[4];

    zero_acc(acc);
    for (int c = 0; c < NCH; c++) {
        __syncthreads();
        a_load<MODE>(in0, in1, c, 0, row0, rows, t, v);
        a_store((char*)sm, SL(c & 1), 0, t, v);
        a_load<MODE>(in0, in1, c, 1, row0, rows, t, v);
        a_store((char*)sm, SL(c & 1), 1, t, v);
        load_w_async(sb, WB(c & 1), o1, kc1 + c * 64, Kpad1, t);
        CP_COMMIT();
        if (c > 0) mma_chunk<K16S1>(sb, SL((c - 1) & 1), WB((c - 1) & 1), acc, m0, n0, lane);
        CP_WAIT0();
    }
    __syncthreads();
    mma_chunk<K16S1>(sb, SL((NCH - 1) & 1), WB((NCH - 1) & 1), acc, m0, n0, lane);
    __syncthreads();

    load_w_async(sb, WB(0), o2, 0, 128, t);
    load_w_async(sb, WB(1), o2, 64, 128, t);
    CP_COMMIT();
    if (EPIG)
        epi_silu_g((char*)sm, acc, b1, pa, pb, m0, n0, lane, row0, rows);
    else
        epi_silu((char*)sm, acc, b1, m0, n0, lane);
    zero_acc(acc);
    CP_WAIT0();
    __syncthreads();
    mma_chunk<4>(sb, SL(0), WB(0), acc, m0, n0, lane);
    mma_chunk<4>(sb, SL(1), WB(1), acc, m0, n0, lane);
    __syncthreads();

    load_w_async(sb, WB(0), o3, 0, 128, t);
    load_w_async(sb, WB(1), o3, 64, 128, t);
    CP_COMMIT();
    epi_silu((char*)sm, acc, b2, m0, n0, lane);
    zero_acc(acc);
    CP_WAIT0();
    __syncthreads();
    mma_chunk<4>(sb, SL(0), WB(0), acc, m0, n0, lane);
    mma_chunk<4>(sb, SL(1), WB(1), acc, m0, n0, lane);
    __syncthreads();
    epi_ln((char*)sm, acc, b3, gam, bet, sRed, m0, n0, wn, lane);
    __syncthreads();

    const float* so = (const float*)sm;
    const int c4 = lane << 2;
    for (int r = w; r < ROWS_CTA; r += 16) {
        int row = row0 + r;
        if (row < rows) {
            const float* sr = so + r * 130 + c4;
            float4 y = make_float4(sr[0], sr[1], sr[2], sr[3]);
            float4 rv = *(const float4*)(resid + (size_t)row * HD + c4);
            y.x += rv.x; y.y += rv.y; y.z += rv.z; y.w += rv.w;
            *(float4*)(out + (size_t)row * HD + c4) = y;
            if (SCAT) {
                float* p = g_agg + (size_t)g_dst[row] * HD + c4;
                asm volatile("red.global.add.v4.f32 [%0], {%1, %2, %3, %4};"
                             :: "l"(p), "f"(y.x), "f"(y.y), "f"(y.z), "f"(y.w)
                             : "memory");
            }
        }
    }
}

// ================= fused emb + edge-block-0 kernel =================
__global__ __launch_bounds__(512, 1) void emb_edge_mlp(
    const float* __restrict__ eattr,
    const float* __restrict__ pa, const float* __restrict__ pb,
    int oEmb1, int oEmb2, int oEmb3, int oE1, int oE2, int oE3,
    const float* __restrict__ eb1, const float* __restrict__ eb2,
    const float* __restrict__ eb3, const float* __restrict__ eg,
    const float* __restrict__ ebe,
    const float* __restrict__ b1, const float* __restrict__ b2,
    const float* __restrict__ b3, const float* __restrict__ gam,
    const float* __restrict__ bet,
    float* __restrict__ out, int rows) {
    extern __shared__ char sm[];
    __shared__ float sRed[2][ROWS_CTA][2];
    const int t = threadIdx.x;
    const uint32_t sb = smem_u32(sm);
    const int lane = t & 31, w = t >> 5;
    const int m0 = (w & 7) * 32, n0 = (w >> 3) * 64, wn = w >> 3;
    const int row0 = blockIdx.x * ROWS_CTA;
    float acc[2][8][4];
    float4 v[4];

    // ===== emb layer 1 (K=16) =====
    zero_acc(acc);
    a_load<0>(eattr, nullptr, 0, 0, row0, rows, t, v);
    a_store((char*)sm, SL(0), 0, t, v);
    a_load<0>(eattr, nullptr, 0, 1, row0, rows, t, v);
    a_store((char*)sm, SL(0), 1, t, v);
    load_w_async(sb, WB(0), oEmb1, 0, 16, t);
    CP_COMMIT();
    CP_WAIT0();
    __syncthreads();
    mma_chunk<1>(sb, SL(0), WB(0), acc, m0, n0, lane);
    __syncthreads();

    // ===== emb layer 2 =====
    load_w_async(sb, WB(0), oEmb2, 0, 128, t);
    load_w_async(sb, WB(1), oEmb2, 64, 128, t);
    CP_COMMIT();
    epi_silu((char*)sm, acc, eb1, m0, n0, lane);
    zero_acc(acc);
    CP_WAIT0();
    __syncthreads();
    mma_chunk<4>(sb, SL(0), WB(0), acc, m0, n0, lane);
    mma_chunk<4>(sb, SL(1), WB(1), acc, m0, n0, lane);
    __syncthreads();

    // ===== emb layer 3 =====
    load_w_async(sb, WB(0), oEmb3, 0, 128, t);
    load_w_async(sb, WB(1), oEmb3, 64, 128, t);
    CP_COMMIT();
    epi_silu((char*)sm, acc, eb2, m0, n0, lane);
    zero_acc(acc);
    CP_WAIT0();
    __syncthreads();
    mma_chunk<4>(sb, SL(0), WB(0), acc, m0, n0, lane);
    mma_chunk<4>(sb, SL(1), WB(1), acc, m0, n0, lane);
    __syncthreads();

    // ===== emb LN -> e (packed into SL tiles + E16 residual) =====
    load_w_async(sb, WB(0), oE1, 256, 384, t);   // edge L1 weights (e section)
    load_w_async(sb, WB(1), oE1, 320, 384, t);
    CP_COMMIT();
    epi_ln_pack((char*)sm, acc, eb3, eg, ebe, sRed, m0, n0, wn, lane);
    zero_acc(acc);
    CP_WAIT0();
    __syncthreads();

    // ===== edge layer 1: e . W1c =====
    mma_chunk<4>(sb, SL(0), WB(0), acc, m0, n0, lane);
    mma_chunk<4>(sb, SL(1), WB(1), acc, m0, n0, lane);
    __syncthreads();

    // ===== edge layer 2 =====
    load_w_async(sb, WB(0), oE2, 0, 128, t);
    load_w_async(sb, WB(1), oE2, 64, 128, t);
    CP_COMMIT();
    epi_silu_g((char*)sm, acc, b1, pa, pb, m0, n0, lane, row0, rows);
    zero_acc(acc);
    CP_WAIT0();
    __syncthreads();
    mma_chunk<4>(sb, SL(0), WB(0), acc, m0, n0, lane);
    mma_chunk<4>(sb, SL(1), WB(1), acc, m0, n0, lane);
    __syncthreads();

    // ===== edge layer 3 =====
    load_w_async(sb, WB(0), oE3, 0, 128, t);
    load_w_async(sb, WB(1), oE3, 64, 128, t);
    CP_COMMIT();
    epi_silu((char*)sm, acc, b2, m0, n0, lane);
    zero_acc(acc);
    CP_WAIT0();
    __syncthreads();
    mma_chunk<4>(sb, SL(0), WB(0), acc, m0, n0, lane);
    mma_chunk<4>(sb, SL(1), WB(1), acc, m0, n0, lane);
    __syncthreads();
    epi_ln((char*)sm, acc, b3, gam, bet, sRed, m0, n0, wn, lane);
    __syncthreads();

    // ===== residual (E16 fp16) + store + fused scatter =====
    const float* so = (const float*)sm;
    const int c4 = lane << 2;
    for (int r = w; r < ROWS_CTA; r += 16) {
        int row = row0 + r;
        if (row < rows) {
            const float* sr = so + r * 130 + c4;
            float4 y = make_float4(sr[0], sr[1], sr[2], sr[3]);
            uint2 ev = *(const uint2*)(sm + E16 + (uint32_t)r * 256u + (uint32_t)(c4 * 2));
            __half2 e0 = *reinterpret_cast<__half2*>(&ev.x);
            __half2 e1 = *reinterpret_cast<__half2*>(&ev.y);
            float2 f0 = __half22float2(e0);
            float2 f1 = __half22float2(e1);
            y.x += f0.x; y.y += f0.y; y.z += f1.x; y.w += f1.y;
            *(float4*)(out + (size_t)row * HD + c4) = y;
            float* p = g_agg + (size_t)g_dst[row] * HD + c4;
            asm volatile("red.global.add.v4.f32 [%0], {%1, %2, %3, %4};"
                         :: "l"(p), "f"(y.x), "f"(y.y), "f"(y.z), "f"(y.w)
                         : "memory");
        }
    }
}

// ================= P precompute =================
__global__ __launch_bounds__(512, 1) void p_gemm(
    const float* __restrict__ x, int wofs, int kc0,
    float* __restrict__ outP, int rows) {
    extern __shared__ char sm[];
    const int t = threadIdx.x;
    const uint32_t sb = smem_u32(sm);
    const int lane = t & 31, w = t >> 5;
    const int m0 = (w & 7) * 32, n0 = (w >> 3) * 64;
    const int row0 = blockIdx.x * ROWS_CTA;
    float acc[2][8][4];
    float4 v[4];
    zero_acc(acc);
    a_load<2>(x, x, 0, 0, row0, rows, t, v);
    a_store((char*)sm, SL(0), 0, t, v);
    a_load<2>(x, x, 0, 1, row0, rows, t, v);
    a_store((char*)sm, SL(0), 1, t, v);
    a_load<2>(x, x, 1, 0, row0, rows, t, v);
    a_store((char*)sm, SL(1), 0, t, v);
    a_load<2>(x, x, 1, 1, row0, rows, t, v);
    a_store((char*)sm, SL(1), 1, t, v);
    load_w_async(sb, WB(0), wofs, kc0, 384, t);
    load_w_async(sb, WB(1), wofs, kc0 + 64, 384, t);
    CP_COMMIT();
    CP_WAIT0();
    __syncthreads();
    mma_chunk<4>(sb, SL(0), WB(0), acc, m0, n0, lane);
    mma_chunk<4>(sb, SL(1), WB(1), acc, m0, n0, lane);
    __syncthreads();
    const int cq = (lane & 3) << 1;
    const int r0l = lane >> 2;
    float* so = (float*)sm;
#pragma unroll
    for (int mi = 0; mi < 2; mi++)
#pragma unroll
        for (int j = 0; j < 8; j++) {
            int c = n0 + j * 8 + cq;
#pragma unroll
            for (int h = 0; h < 2; h++) {
                int r = m0 + mi * 16 + r0l + 8 * h;
                so[r * 130 + c]     = acc[mi][j][2 * h];
                so[r * 130 + c + 1] = acc[mi][j][2 * h + 1];
            }
        }
    __syncthreads();
    const int c4 = lane << 2;
    for (int r = w; r < ROWS_CTA; r += 16) {
        int row = row0 + r;
        if (row < rows) {
            const float* sr = so + r * 130 + c4;
            float4 y = make_float4(sr[0], sr[1], sr[2], sr[3]);
            *(float4*)(outP + (size_t)row * HD + c4) = y;
        }
    }
}

// ================= aggregation buffer zero =================
__global__ void zero_agg_kernel() {
    size_t i = (size_t)blockIdx.x * blockDim.x + threadIdx.x;
    if (i < (size_t)NN * HD) g_agg[i] = 0.f;
}

// ================= launch =================
extern "C" void kernel_launch(void* const* d_in, const int* in_sizes, int n_in,
                              void* d_out, int out_size) {
    const float* x_in    = (const float*)d_in[0];
    const int*   eidx    = (const int*)d_in[1];
    const float* eattr   = (const float*)d_in[2];
    const float* emb_W1  = (const float*)d_in[3];
    const float* emb_b1  = (const float*)d_in[4];
    const float* emb_W2  = (const float*)d_in[5];
    const float* emb_b2  = (const float*)d_in[6];
    const float* emb_W3  = (const float*)d_in[7];
    const float* emb_b3  = (const float*)d_in[8];
    const float* emb_g   = (const float*)d_in[9];
    const float* emb_be  = (const float*)d_in[10];
    const float* edge_W1 = (const float*)d_in[11];
    const float* edge_b1 = (const float*)d_in[12];
    const float* edge_W2 = (const float*)d_in[13];
    const float* edge_b2 = (const float*)d_in[14];
    const float* edge_W3 = (const float*)d_in[15];
    const float* edge_b3 = (const float*)d_in[16];
    const float* edge_g  = (const float*)d_in[17];
    const float* edge_be = (const float*)d_in[18];
    const float* node_W1 = (const float*)d_in[19];
    const float* node_b1 = (const float*)d_in[20];
    const float* node_W2 = (const float*)d_in[21];
    const float* node_b2 = (const float*)d_in[22];
    const float* node_W3 = (const float*)d_in[23];
    const float* node_b3 = (const float*)d_in[24];
    const float* node_g  = (const float*)d_in[25];
    const float* node_be = (const float*)d_in[26];

    float* out_x = (float*)d_out;
    float* out_e = (float*)d_out + (size_t)NN * HD;

    float *eB, *agg, *xbuf, *Pa, *Pb;
    cudaGetSymbolAddress((void**)&eB, g_eB);
    cudaGetSymbolAddress((void**)&agg, g_agg);
    cudaGetSymbolAddress((void**)&xbuf, g_x);
    cudaGetSymbolAddress((void**)&Pa, g_Pa);
    cudaGetSymbolAddress((void**)&Pb, g_Pb);

    cudaFuncSetAttribute((const void*)emb_edge_mlp, cudaFuncAttributeMaxDynamicSharedMemorySize, SMEM_FUSED);
    cudaFuncSetAttribute((const void*)mma_mlp<3, 2, 4, 1, 1>, cudaFuncAttributeMaxDynamicSharedMemorySize, SMEM_DYN);
    cudaFuncSetAttribute((const void*)mma_mlp<2, 4, 4, 0, 0>, cudaFuncAttributeMaxDynamicSharedMemorySize, SMEM_DYN);
    cudaFuncSetAttribute((const void*)p_gemm, cudaFuncAttributeMaxDynamicSharedMemorySize, SMEM_DYN);

    // index prep (clamped)
    detect_kernel<<<1, 256>>>(eidx);
    convert_kernel<<<(NE + 255) / 256, 256>>>(eidx);

    // pool offsets (elements)
    const int oEmb1 = 0, oEmb2 = 8192, oEmb3 = 24576;
    int oE1[2], oE2[2], oE3[2], oN1[2], oN2[2], oN3[2];
    int base = 40960;
    for (int l = 0; l < 2; l++) {
        oE1[l] = base;
        oE2[l] = base + 49152;
        oE3[l] = base + 65536;
        oN1[l] = base + 81920;
        oN2[l] = base + 114688;
        oN3[l] = base + 131072;
        base += 147456;
    }

    WJobs jobs;
    int ji = 0;
    jobs.j[ji++] = {emb_W1, 16, 16, oEmb1};
    jobs.j[ji++] = {emb_W2, 128, 128, oEmb2};
    jobs.j[ji++] = {emb_W3, 128, 128, oEmb3};
    for (int l = 0; l < 2; l++) {
        jobs.j[ji++] = {edge_W1 + (size_t)l * 3 * HD * HD, 384, 384, oE1[l]};
        jobs.j[ji++] = {edge_W2 + (size_t)l * HD * HD, 128, 128, oE2[l]};
        jobs.j[ji++] = {edge_W3 + (size_t)l * HD * HD, 128, 128, oE3[l]};
        jobs.j[ji++] = {node_W1 + (size_t)l * 2 * HD * HD, 256, 256, oN1[l]};
        jobs.j[ji++] = {node_W2 + (size_t)l * HD * HD, 128, 128, oN2[l]};
        jobs.j[ji++] = {node_W3 + (size_t)l * HD * HD, 128, 128, oN3[l]};
    }
    dim3 cg((128 * 384 + 255) / 256, NJOBS);
    conv_w_kernel<<<cg, 256>>>(jobs);

    const int edge_blocks = (NE + ROWS_CTA - 1) / ROWS_CTA;   // 1563
    const int node_blocks = (NN + ROWS_CTA - 1) / ROWS_CTA;   // 98
    const int nthr_blocks = (int)(((size_t)NN * HD + 255) / 256);

    const float* x_cur = x_in;
    float* e_cur = nullptr;
    for (int l = 0; l < 2; l++) {
        float* e_out = (l == 0) ? eB : out_e;
        float* x_out = (l == 0) ? xbuf : out_x;

        // Pa = x . W1[:,0:128] (dst), Pb = x . W1[:,128:256] (src)
        p_gemm<<<node_blocks, 512, SMEM_DYN>>>(x_cur, oE1[l], 0, Pa, NN);
        p_gemm<<<node_blocks, 512, SMEM_DYN>>>(x_cur, oE1[l], 128, Pb, NN);

        zero_agg_kernel<<<nthr_blocks, 256>>>();

        if (l == 0) {
            // fused: e = embMLP(edge_attr); e_new = edgeMLP + e; agg += e_new
            emb_edge_mlp<<<edge_blocks, 512, SMEM_FUSED>>>(
                eattr, Pa, Pb, oEmb1, oEmb2, oEmb3, oE1[0], oE2[0], oE3[0],
                emb_b1, emb_b2, emb_b3, emb_g, emb_be,
                edge_b1, edge_b2, edge_b3, edge_g, edge_be, e_out, NE);
        } else {
            mma_mlp<3, 2, 4, 1, 1><<<edge_blocks, 512, SMEM_DYN>>>(
                nullptr, e_cur, Pa, Pb, oE1[l], 256, oE2[l], oE3[l], 384,
                edge_b1 + l * HD, edge_b2 + l * HD, edge_b3 + l * HD,
                edge_g + l * HD, edge_be + l * HD, e_cur, e_out, NE);
        }

        // x = MLP([x | agg]) + x
        mma_mlp<2, 4, 4, 0, 0><<<node_blocks, 512, SMEM_DYN>>>(
            x_cur, agg, nullptr, nullptr, oN1[l], 0, oN2[l], oN3[l], 256,
            node_b1 + l * HD, node_b2 + l * HD, node_b3 + l * HD,
            node_g + l * HD, node_be + l * HD, x_cur, x_out, NN);

        e_cur = e_out;
        x_cur = x_out;
    }
}